// round 2
// baseline (speedup 1.0000x reference)
#include <cuda_runtime.h>
#include <cuda_bf16.h>
#include <cstdint>
#include <cstdio>

// Problem constants
#define T_LEN 4096
#define BATCH 2
#define DMODEL 1024
#define NH 8
#define DFH 128
#define DIH 128
#define BH (BATCH*NH)
#define MROWS (BATCH*T_LEN)

// ---------------- scratch (device globals; no runtime allocation) ----------------
__device__ float g_q[BH*T_LEN*DFH];   // silu(xWq^T) * DF^-0.5, layout [bh][t][f]
__device__ float g_e[BH*T_LEN*DFH];   // sigmoid(xWf^T) = exp(log_sigmoid)
__device__ float g_k[BH*T_LEN*DFH];   // 1 - sigmoid
__device__ float g_v[BH*T_LEN*DIH];   // xWi^T
__device__ float g_o[(size_t)MROWS*DMODEL]; // recurrence output [b][t][h*128+d]
__device__ float g_invr[MROWS];

// ---------------- cp.async helper ----------------
__device__ __forceinline__ void cp16(void* s, const void* g) {
    uint32_t sa = (uint32_t)__cvta_generic_to_shared(s);
    asm volatile("cp.async.ca.shared.global [%0], [%1], 16;\n" :: "r"(sa), "l"(g));
}

// =====================================================================
// Kernel 1: fused QFV projection GEMM.  C[m][n] = sum_k X[m][k]*W[n][k]
// M=8192, N=3072 (Wq|Wf|Wi), K=1024.  128x128x16 tiles, 8x8 microtile.
// =====================================================================
#define BMt 128
#define BNt 128
#define BKt 16

__global__ void __launch_bounds__(256, 2) gemm_qfi(
    const float* __restrict__ X,
    const float* __restrict__ Wq,
    const float* __restrict__ Wf,
    const float* __restrict__ Wi)
{
    __shared__ float As[2][BKt][BMt + 4];
    __shared__ float Bs[2][BKt][BNt + 4];

    const int tid   = threadIdx.x;
    const int ntile = blockIdx.x;      // 0..23
    const int mtile = blockIdx.y;      // 0..63
    const int mat   = ntile >> 3;      // 0=q,1=f,2=i
    const float* __restrict__ W = (mat == 0) ? Wq : (mat == 1) ? Wf : Wi;
    const int h  = ntile & 7;
    const int m0 = mtile * BMt;
    const int n0 = h * BNt;

    const int tx = tid & 15, ty = tid >> 4;
    const int lrow0 = tid >> 2;        // 0..63
    const int lc4   = tid & 3;

    float4 ra[2], rb[2];

    auto loadg = [&](int kt) {
        const int k0 = kt * BKt + lc4 * 4;
#pragma unroll
        for (int p = 0; p < 2; p++) {
            int row = lrow0 + p * 64;
            ra[p] = *(const float4*)(X + (size_t)(m0 + row) * DMODEL + k0);
            rb[p] = *(const float4*)(W + (size_t)(n0 + row) * DMODEL + k0);
        }
    };
    auto sts = [&](int buf) {
#pragma unroll
        for (int p = 0; p < 2; p++) {
            int row = lrow0 + p * 64;
            As[buf][lc4 * 4 + 0][row] = ra[p].x;
            As[buf][lc4 * 4 + 1][row] = ra[p].y;
            As[buf][lc4 * 4 + 2][row] = ra[p].z;
            As[buf][lc4 * 4 + 3][row] = ra[p].w;
            Bs[buf][lc4 * 4 + 0][row] = rb[p].x;
            Bs[buf][lc4 * 4 + 1][row] = rb[p].y;
            Bs[buf][lc4 * 4 + 2][row] = rb[p].z;
            Bs[buf][lc4 * 4 + 3][row] = rb[p].w;
        }
    };

    float acc[8][8];
#pragma unroll
    for (int i = 0; i < 8; i++)
#pragma unroll
        for (int j = 0; j < 8; j++) acc[i][j] = 0.f;

    loadg(0);
    sts(0);
    __syncthreads();

    int buf = 0;
    for (int kt = 0; kt < DMODEL / BKt; kt++) {
        if (kt < DMODEL / BKt - 1) loadg(kt + 1);
#pragma unroll
        for (int kk = 0; kk < BKt; kk++) {
            float4 a0 = *(const float4*)&As[buf][kk][ty * 8];
            float4 a1 = *(const float4*)&As[buf][kk][ty * 8 + 4];
            float4 b0 = *(const float4*)&Bs[buf][kk][tx * 8];
            float4 b1 = *(const float4*)&Bs[buf][kk][tx * 8 + 4];
            float av[8] = {a0.x, a0.y, a0.z, a0.w, a1.x, a1.y, a1.z, a1.w};
            float bv[8] = {b0.x, b0.y, b0.z, b0.w, b1.x, b1.y, b1.z, b1.w};
#pragma unroll
            for (int i = 0; i < 8; i++)
#pragma unroll
                for (int j = 0; j < 8; j++)
                    acc[i][j] = fmaf(av[i], bv[j], acc[i][j]);
        }
        if (kt < DMODEL / BKt - 1) {
            sts(buf ^ 1);
            __syncthreads();
            buf ^= 1;
        }
    }

    // epilogue: activation + scatter into [bh][t][f] layout
    const float qscale = 0.08838834764831845f; // 128^-0.5
#pragma unroll
    for (int i = 0; i < 8; i++) {
        int m = m0 + ty * 8 + i;
        int b = m >> 12;
        int t = m & (T_LEN - 1);
        size_t base = (((size_t)(b * NH + h)) * T_LEN + t) * DFH + tx * 8;
#pragma unroll
        for (int j = 0; j < 8; j++) {
            float y = acc[i][j];
            if (mat == 0) {
                float s = 1.f / (1.f + expf(-y));
                g_q[base + j] = y * s * qscale;
            } else if (mat == 1) {
                float a = 1.f / (1.f + expf(-y));
                g_e[base + j] = a;
                g_k[base + j] = 1.f - a;
            } else {
                g_v[base + j] = y;
            }
        }
    }
}

// =====================================================================
// Kernel 2: recurrence.  grid (16 dchunks, 16 bh), 128 threads.
// CTA owns state [128f x 8d]; thread owns [8f x 1d] in regs.
// cp.async double-buffered staging of 8 timesteps of e/k/q/v.
// f-reduction of o via padded shared buffer, amortized per 8 steps.
// =====================================================================
__global__ void __launch_bounds__(128) recur_kernel()
{
    __shared__ float sE[2][8][128];
    __shared__ float sK[2][8][128];
    __shared__ float sQ[2][8][128];
    __shared__ float sV[2][8][8];
    __shared__ float sO[8 * 8 * 17 + 2];

    const int tid    = threadIdx.x;
    const int dchunk = blockIdx.x;   // 0..15
    const int bh     = blockIdx.y;   // 0..15
    const int d0 = dchunk * 8;
    const int fg = tid >> 3, dl = tid & 7, f0 = fg * 8;
    const int b = bh >> 3, h = bh & 7;
    const size_t bhbase = (size_t)bh * T_LEN * DFH;

    float S[8];
#pragma unroll
    for (int j = 0; j < 8; j++) S[j] = 0.f;

    auto stage = [&](int buf, int t0) {
#pragma unroll
        for (int p = 0; p < 2; p++) {
            int c = tid + p * 128;
            int s = c >> 5;
            int off = (c & 31) * 4;
            size_t gi = bhbase + (size_t)(t0 + s) * DFH + off;
            cp16(&sE[buf][s][off], g_e + gi);
            cp16(&sK[buf][s][off], g_k + gi);
            cp16(&sQ[buf][s][off], g_q + gi);
        }
        if (tid < 16) {
            int s = tid >> 1, off = (tid & 1) * 4;
            cp16(&sV[buf][s][off], g_v + bhbase + (size_t)(t0 + s) * DIH + d0 + off);
        }
    };

    stage(0, 0);
    asm volatile("cp.async.commit_group;\n");

    const int NBLK = T_LEN / 8;  // 512
    for (int blk = 0; blk < NBLK; blk++) {
        if (blk + 1 < NBLK) {
            stage((blk + 1) & 1, (blk + 1) * 8);
            asm volatile("cp.async.commit_group;\n");
            asm volatile("cp.async.wait_group 1;\n");
        } else {
            asm volatile("cp.async.wait_group 0;\n");
        }
        __syncthreads();

        const int cur = blk & 1;
#pragma unroll
        for (int s = 0; s < 8; s++) {
            float4 e0 = *(const float4*)&sE[cur][s][f0];
            float4 e1 = *(const float4*)&sE[cur][s][f0 + 4];
            float4 k0 = *(const float4*)&sK[cur][s][f0];
            float4 k1 = *(const float4*)&sK[cur][s][f0 + 4];
            float4 q0 = *(const float4*)&sQ[cur][s][f0];
            float4 q1 = *(const float4*)&sQ[cur][s][f0 + 4];
            float vv = sV[cur][s][dl];
            float ev[8], kv[8], qv[8];
            *(float4*)&ev[0] = e0; *(float4*)&ev[4] = e1;
            *(float4*)&kv[0] = k0; *(float4*)&kv[4] = k1;
            *(float4*)&qv[0] = q0; *(float4*)&qv[4] = q1;
            float o = 0.f;
#pragma unroll
            for (int j = 0; j < 8; j++) {
                S[j] = fmaf(ev[j], S[j], kv[j] * vv);
                o = fmaf(qv[j], S[j], o);
            }
            sO[(s * 8 + dl) * 17 + fg] = o;
        }
        __syncthreads();

        if (tid < 64) {
            const int tt = tid >> 3, dd = tid & 7;
            float acc = 0.f;
#pragma unroll
            for (int g2 = 0; g2 < 16; g2++) acc += sO[(tt * 8 + dd) * 17 + g2];
            const int trow = blk * 8 + tt;
            g_o[((size_t)(b * T_LEN + trow)) * DMODEL + h * DFH + d0 + dd] = acc;
        }
    }
}

// =====================================================================
// Kernel 3: per-row inverse RMS of g_o
// =====================================================================
__global__ void rms_kernel()
{
    __shared__ float red[8];
    const int row = blockIdx.x;
    const int tid = threadIdx.x;   // 256
    const float4* p = (const float4*)(g_o + (size_t)row * DMODEL);
    float4 v = p[tid];
    float s = v.x * v.x + v.y * v.y + v.z * v.z + v.w * v.w;
#pragma unroll
    for (int o = 16; o > 0; o >>= 1) s += __shfl_xor_sync(0xffffffffu, s, o);
    if ((tid & 31) == 0) red[tid >> 5] = s;
    __syncthreads();
    if (tid == 0) {
        float t = 0.f;
#pragma unroll
        for (int w = 0; w < 8; w++) t += red[w];
        g_invr[row] = rsqrtf(t * (1.0f / DMODEL) + 1e-5f);
    }
}

// =====================================================================
// Kernel 4: output projection. out = (o * invr * gw) @ Wo^T
// =====================================================================
__global__ void __launch_bounds__(256, 2) gemm_out(
    const float* __restrict__ Wo,
    const float* __restrict__ gw,
    float* __restrict__ out)
{
    __shared__ float As[2][BKt][BMt + 4];
    __shared__ float Bs[2][BKt][BNt + 4];

    const int tid   = threadIdx.x;
    const int ntile = blockIdx.x;  // 0..7
    const int mtile = blockIdx.y;  // 0..63
    const int m0 = mtile * BMt;
    const int n0 = ntile * BNt;
    const int tx = tid & 15, ty = tid >> 4;
    const int lrow0 = tid >> 2;
    const int lc4   = tid & 3;

    const float inv0 = g_invr[m0 + lrow0];
    const float inv1 = g_invr[m0 + lrow0 + 64];

    float4 ra[2], rb[2];

    auto loadg = [&](int kt) {
        const int k0 = kt * BKt + lc4 * 4;
        float4 gv = *(const float4*)(gw + k0);
#pragma unroll
        for (int p = 0; p < 2; p++) {
            int row = lrow0 + p * 64;
            float iv = p ? inv1 : inv0;
            float4 a = *(const float4*)(g_o + (size_t)(m0 + row) * DMODEL + k0);
            a.x *= iv * gv.x; a.y *= iv * gv.y; a.z *= iv * gv.z; a.w *= iv * gv.w;
            ra[p] = a;
            rb[p] = *(const float4*)(Wo + (size_t)(n0 + row) * DMODEL + k0);
        }
    };
    auto sts = [&](int buf) {
#pragma unroll
        for (int p = 0; p < 2; p++) {
            int row = lrow0 + p * 64;
            As[buf][lc4 * 4 + 0][row] = ra[p].x;
            As[buf][lc4 * 4 + 1][row] = ra[p].y;
            As[buf][lc4 * 4 + 2][row] = ra[p].z;
            As[buf][lc4 * 4 + 3][row] = ra[p].w;
            Bs[buf][lc4 * 4 + 0][row] = rb[p].x;
            Bs[buf][lc4 * 4 + 1][row] = rb[p].y;
            Bs[buf][lc4 * 4 + 2][row] = rb[p].z;
            Bs[buf][lc4 * 4 + 3][row] = rb[p].w;
        }
    };

    float acc[8][8];
#pragma unroll
    for (int i = 0; i < 8; i++)
#pragma unroll
        for (int j = 0; j < 8; j++) acc[i][j] = 0.f;

    loadg(0);
    sts(0);
    __syncthreads();

    int buf = 0;
    for (int kt = 0; kt < DMODEL / BKt; kt++) {
        if (kt < DMODEL / BKt - 1) loadg(kt + 1);
#pragma unroll
        for (int kk = 0; kk < BKt; kk++) {
            float4 a0 = *(const float4*)&As[buf][kk][ty * 8];
            float4 a1 = *(const float4*)&As[buf][kk][ty * 8 + 4];
            float4 b0 = *(const float4*)&Bs[buf][kk][tx * 8];
            float4 b1 = *(const float4*)&Bs[buf][kk][tx * 8 + 4];
            float av[8] = {a0.x, a0.y, a0.z, a0.w, a1.x, a1.y, a1.z, a1.w};
            float bv[8] = {b0.x, b0.y, b0.z, b0.w, b1.x, b1.y, b1.z, b1.w};
#pragma unroll
            for (int i = 0; i < 8; i++)
#pragma unroll
                for (int j = 0; j < 8; j++)
                    acc[i][j] = fmaf(av[i], bv[j], acc[i][j]);
        }
        if (kt < DMODEL / BKt - 1) {
            sts(buf ^ 1);
            __syncthreads();
            buf ^= 1;
        }
    }

#pragma unroll
    for (int i = 0; i < 8; i++) {
        int m = m0 + ty * 8 + i;
        float* dst = out + (size_t)m * DMODEL + n0 + tx * 8;
        float4 s0 = {acc[i][0], acc[i][1], acc[i][2], acc[i][3]};
        float4 s1 = {acc[i][4], acc[i][5], acc[i][6], acc[i][7]};
        *(float4*)(dst)     = s0;
        *(float4*)(dst + 4) = s1;
    }
}

// =====================================================================
extern "C" void kernel_launch(void* const* d_in, const int* in_sizes, int n_in,
                              void* d_out, int out_size)
{
    const float* x  = (const float*)d_in[0];
    const float* Wq = (const float*)d_in[1];
    const float* Wf = (const float*)d_in[2];
    const float* Wi = (const float*)d_in[3];
    const float* gw = (const float*)d_in[4];
    const float* Wo = (const float*)d_in[5];
    float* out = (float*)d_out;

    gemm_qfi<<<dim3(24, 64), 256>>>(x, Wq, Wf, Wi);
    recur_kernel<<<dim3(16, 16), 128>>>();
    rms_kernel<<<MROWS, 256>>>();
    gemm_out<<<dim3(8, 64), 256>>>(Wo, gw, out);
}

// round 3
// speedup vs baseline: 1.6039x; 1.6039x over previous
#include <cuda_runtime.h>
#include <cuda_bf16.h>
#include <cstdint>
#include <cstdio>

// Problem constants
#define T_LEN 4096
#define BATCH 2
#define DMODEL 1024
#define NH 8
#define DFH 128
#define DIH 128
#define BH (BATCH*NH)
#define MROWS (BATCH*T_LEN)

// ---------------- scratch (device globals; no runtime allocation) ----------------
__device__ float g_q[BH*T_LEN*DFH];   // silu(xWq^T) * DF^-0.5, layout [bh][t][f]
__device__ float g_e[BH*T_LEN*DFH];   // sigmoid(xWf^T)
__device__ float g_k[BH*T_LEN*DFH];   // 1 - sigmoid
__device__ float g_v[BH*T_LEN*DIH];   // xWi^T
__device__ float g_o[(size_t)MROWS*DMODEL]; // recurrence output [b][t][h*128+d]

// bf16 hi/lo split operands
__device__ __nv_bfloat16 g_xh[(size_t)MROWS*DMODEL];
__device__ __nv_bfloat16 g_xl[(size_t)MROWS*DMODEL];
__device__ __nv_bfloat16 g_wh[(size_t)3*DMODEL*DMODEL];  // Wq|Wf|Wi rows
__device__ __nv_bfloat16 g_wl[(size_t)3*DMODEL*DMODEL];
__device__ __nv_bfloat16 g_oh[(size_t)MROWS*DMODEL];     // rms-scaled o
__device__ __nv_bfloat16 g_ol[(size_t)MROWS*DMODEL];
__device__ __nv_bfloat16 g_woh[(size_t)DMODEL*DMODEL];
__device__ __nv_bfloat16 g_wol[(size_t)DMODEL*DMODEL];

// ---------------- helpers ----------------
__device__ __forceinline__ void cp16(void* s, const void* g) {
    uint32_t sa = (uint32_t)__cvta_generic_to_shared(s);
    asm volatile("cp.async.ca.shared.global [%0], [%1], 16;\n" :: "r"(sa), "l"(g));
}
__device__ __forceinline__ uint32_t smem_u32(const void* p) {
    return (uint32_t)__cvta_generic_to_shared(p);
}

#define MMA_BF16(accp, A, B)                                                 \
    asm("mma.sync.aligned.m16n8k16.row.col.f32.bf16.bf16.f32 "               \
        "{%0,%1,%2,%3}, {%4,%5,%6,%7}, {%8,%9}, {%0,%1,%2,%3};"              \
        : "+f"((accp)[0]), "+f"((accp)[1]), "+f"((accp)[2]), "+f"((accp)[3]) \
        : "r"((A)[0]), "r"((A)[1]), "r"((A)[2]), "r"((A)[3]),                \
          "r"((B)[0]), "r"((B)[1]))

// =====================================================================
// split: fp32 -> (bf16 hi, bf16 lo).  dst_sel: 0=X, 1=W(off), 2=Wo
// =====================================================================
__global__ void split_kernel(const float* __restrict__ src, int dst_sel,
                             int off, int n4)
{
    int i = blockIdx.x * blockDim.x + threadIdx.x;
    if (i >= n4) return;
    __nv_bfloat16 *hi, *lo;
    if (dst_sel == 0)      { hi = g_xh;        lo = g_xl; }
    else if (dst_sel == 1) { hi = g_wh + off;  lo = g_wl + off; }
    else                   { hi = g_woh;       lo = g_wol; }

    float4 v = ((const float4*)src)[i];
    __nv_bfloat16 h0 = __float2bfloat16(v.x);
    __nv_bfloat16 h1 = __float2bfloat16(v.y);
    __nv_bfloat16 h2 = __float2bfloat16(v.z);
    __nv_bfloat16 h3 = __float2bfloat16(v.w);
    __nv_bfloat16 l0 = __float2bfloat16(v.x - __bfloat162float(h0));
    __nv_bfloat16 l1 = __float2bfloat16(v.y - __bfloat162float(h1));
    __nv_bfloat16 l2 = __float2bfloat16(v.z - __bfloat162float(h2));
    __nv_bfloat16 l3 = __float2bfloat16(v.w - __bfloat162float(h3));
    __nv_bfloat162* ph = (__nv_bfloat162*)(hi + (size_t)4 * i);
    __nv_bfloat162* pl = (__nv_bfloat162*)(lo + (size_t)4 * i);
    ph[0] = __nv_bfloat162(h0, h1); ph[1] = __nv_bfloat162(h2, h3);
    pl[0] = __nv_bfloat162(l0, l1); pl[1] = __nv_bfloat162(l2, l3);
}

// =====================================================================
// bf16x3 tensor-core GEMM.  C[m][n] = sum_k A[m][k]*B[n][k]  (fp32 acc)
// EPI=0: A=X split, B=W split (3072 rows), epilogue silu/sigmoid scatter
// EPI=1: A=o split, B=Wo split, epilogue -> out
// CTA 128x128, BK=16, 8 warps (2x4) of 64x32, double-buffered cp.async.
// =====================================================================
template<int EPI>
__global__ void __launch_bounds__(256) gemm_bf3(float* __restrict__ out)
{
    __shared__ __nv_bfloat16 sAh[2][128][24];   // rows padded to 48B: conflict-free ldmatrix
    __shared__ __nv_bfloat16 sAl[2][128][24];
    __shared__ __nv_bfloat16 sBh[2][128][16];
    __shared__ __nv_bfloat16 sBl[2][128][16];

    const __nv_bfloat16* __restrict__ Ah = (EPI == 0) ? g_xh : g_oh;
    const __nv_bfloat16* __restrict__ Al = (EPI == 0) ? g_xl : g_ol;
    const __nv_bfloat16* __restrict__ Bh = (EPI == 0) ? g_wh : g_woh;
    const __nv_bfloat16* __restrict__ Bl = (EPI == 0) ? g_wl : g_wol;

    const int tid  = threadIdx.x;
    const int wid  = tid >> 5, lane = tid & 31;
    const int wm   = wid >> 2, wn = wid & 3;
    const int m0   = blockIdx.y * 128;
    const int n0   = blockIdx.x * 128;

    const int sr = tid >> 1, sc = tid & 1;

    auto stage = [&](int buf, int kt) {
        const int kb = kt * 16 + sc * 8;
        cp16(&sAh[buf][sr][sc * 8], Ah + (size_t)(m0 + sr) * DMODEL + kb);
        cp16(&sAl[buf][sr][sc * 8], Al + (size_t)(m0 + sr) * DMODEL + kb);
        cp16(&sBh[buf][sr][sc * 8], Bh + (size_t)(n0 + sr) * DMODEL + kb);
        cp16(&sBl[buf][sr][sc * 8], Bl + (size_t)(n0 + sr) * DMODEL + kb);
    };

    float acc[4][4][4];
#pragma unroll
    for (int i = 0; i < 4; i++)
#pragma unroll
        for (int j = 0; j < 4; j++)
#pragma unroll
            for (int r = 0; r < 4; r++) acc[i][j][r] = 0.f;

    // ldmatrix lane geometry
    const int aRow  = wm * 64 + ((lane >> 3) & 1) * 8 + (lane & 7); // + mf*16
    const int aCol  = (lane >> 4) * 8;
    const int l15   = lane & 15;
    const int bRow  = wn * 32 + (l15 & 7);                          // + nf*8
    const int bHalf = (l15 >> 3) * 8;

    stage(0, 0);
    asm volatile("cp.async.commit_group;\n");

    const int NKT = DMODEL / 16;  // 64
    for (int kt = 0; kt < NKT; kt++) {
        if (kt < NKT - 1) {
            stage((kt + 1) & 1, kt + 1);
            asm volatile("cp.async.commit_group;\n");
            asm volatile("cp.async.wait_group 1;\n");
        } else {
            asm volatile("cp.async.wait_group 0;\n");
        }
        __syncthreads();
        const int buf = kt & 1;

        uint32_t bh[4][2], bl[4][2];
#pragma unroll
        for (int nf = 0; nf < 4; nf++) {
            uint32_t ah_ = smem_u32(&sBh[buf][bRow + nf * 8][bHalf]);
            asm volatile("ldmatrix.sync.aligned.m8n8.x2.shared.b16 {%0,%1}, [%2];"
                         : "=r"(bh[nf][0]), "=r"(bh[nf][1]) : "r"(ah_));
            uint32_t al_ = smem_u32(&sBl[buf][bRow + nf * 8][bHalf]);
            asm volatile("ldmatrix.sync.aligned.m8n8.x2.shared.b16 {%0,%1}, [%2];"
                         : "=r"(bl[nf][0]), "=r"(bl[nf][1]) : "r"(al_));
        }
#pragma unroll
        for (int mf = 0; mf < 4; mf++) {
            uint32_t a[4], al2[4];
            uint32_t pa = smem_u32(&sAh[buf][aRow + mf * 16][aCol]);
            asm volatile("ldmatrix.sync.aligned.m8n8.x4.shared.b16 {%0,%1,%2,%3}, [%4];"
                         : "=r"(a[0]), "=r"(a[1]), "=r"(a[2]), "=r"(a[3]) : "r"(pa));
            uint32_t pl = smem_u32(&sAl[buf][aRow + mf * 16][aCol]);
            asm volatile("ldmatrix.sync.aligned.m8n8.x4.shared.b16 {%0,%1,%2,%3}, [%4];"
                         : "=r"(al2[0]), "=r"(al2[1]), "=r"(al2[2]), "=r"(al2[3]) : "r"(pl));
            // combo-major so dependent MMAs on the same acc are 4 apart
#pragma unroll
            for (int nf = 0; nf < 4; nf++) MMA_BF16(acc[mf][nf], a,   bh[nf]);
#pragma unroll
            for (int nf = 0; nf < 4; nf++) MMA_BF16(acc[mf][nf], a,   bl[nf]);
#pragma unroll
            for (int nf = 0; nf < 4; nf++) MMA_BF16(acc[mf][nf], al2, bh[nf]);
        }
        __syncthreads();
    }

    // epilogue
    const int g = lane >> 2, tg = lane & 3;
    if (EPI == 0) {
        const int mat = blockIdx.x >> 3;
        const int h   = blockIdx.x & 7;
        const float qscale = 0.08838834764831845f; // 128^-0.5
#pragma unroll
        for (int mf = 0; mf < 4; mf++)
#pragma unroll
        for (int nf = 0; nf < 4; nf++)
#pragma unroll
        for (int half = 0; half < 2; half++) {
            int m = m0 + wm * 64 + mf * 16 + g + half * 8;
            int f = wn * 32 + nf * 8 + tg * 2;
            int b = m >> 12, t = m & (T_LEN - 1);
            size_t base = (((size_t)(b * NH + h)) * T_LEN + t) * DFH + f;
            float y0 = acc[mf][nf][half * 2 + 0];
            float y1 = acc[mf][nf][half * 2 + 1];
            if (mat == 0) {
                float s0 = 1.f / (1.f + expf(-y0));
                float s1 = 1.f / (1.f + expf(-y1));
                *(float2*)(g_q + base) = make_float2(y0 * s0 * qscale, y1 * s1 * qscale);
            } else if (mat == 1) {
                float a0 = 1.f / (1.f + expf(-y0));
                float a1 = 1.f / (1.f + expf(-y1));
                *(float2*)(g_e + base) = make_float2(a0, a1);
                *(float2*)(g_k + base) = make_float2(1.f - a0, 1.f - a1);
            } else {
                *(float2*)(g_v + base) = make_float2(y0, y1);
            }
        }
    } else {
#pragma unroll
        for (int mf = 0; mf < 4; mf++)
#pragma unroll
        for (int nf = 0; nf < 4; nf++)
#pragma unroll
        for (int half = 0; half < 2; half++) {
            int m = m0 + wm * 64 + mf * 16 + g + half * 8;
            int n = n0 + wn * 32 + nf * 8 + tg * 2;
            *(float2*)(out + (size_t)m * DMODEL + n) =
                make_float2(acc[mf][nf][half * 2 + 0], acc[mf][nf][half * 2 + 1]);
        }
    }
}

// =====================================================================
// recurrence (unchanged from passing R2 version)
// =====================================================================
__global__ void __launch_bounds__(128) recur_kernel()
{
    __shared__ float sE[2][8][128];
    __shared__ float sK[2][8][128];
    __shared__ float sQ[2][8][128];
    __shared__ float sV[2][8][8];
    __shared__ float sO[8 * 8 * 17 + 2];

    const int tid    = threadIdx.x;
    const int dchunk = blockIdx.x;
    const int bh     = blockIdx.y;
    const int d0 = dchunk * 8;
    const int fg = tid >> 3, dl = tid & 7, f0 = fg * 8;
    const int b = bh >> 3, h = bh & 7;
    const size_t bhbase = (size_t)bh * T_LEN * DFH;

    float S[8];
#pragma unroll
    for (int j = 0; j < 8; j++) S[j] = 0.f;

    auto stage = [&](int buf, int t0) {
#pragma unroll
        for (int p = 0; p < 2; p++) {
            int c = tid + p * 128;
            int s = c >> 5;
            int off = (c & 31) * 4;
            size_t gi = bhbase + (size_t)(t0 + s) * DFH + off;
            cp16(&sE[buf][s][off], g_e + gi);
            cp16(&sK[buf][s][off], g_k + gi);
            cp16(&sQ[buf][s][off], g_q + gi);
        }
        if (tid < 16) {
            int s = tid >> 1, off = (tid & 1) * 4;
            cp16(&sV[buf][s][off], g_v + bhbase + (size_t)(t0 + s) * DIH + d0 + off);
        }
    };

    stage(0, 0);
    asm volatile("cp.async.commit_group;\n");

    const int NBLK = T_LEN / 8;
    for (int blk = 0; blk < NBLK; blk++) {
        if (blk + 1 < NBLK) {
            stage((blk + 1) & 1, (blk + 1) * 8);
            asm volatile("cp.async.commit_group;\n");
            asm volatile("cp.async.wait_group 1;\n");
        } else {
            asm volatile("cp.async.wait_group 0;\n");
        }
        __syncthreads();

        const int cur = blk & 1;
#pragma unroll
        for (int s = 0; s < 8; s++) {
            float4 e0 = *(const float4*)&sE[cur][s][f0];
            float4 e1 = *(const float4*)&sE[cur][s][f0 + 4];
            float4 k0 = *(const float4*)&sK[cur][s][f0];
            float4 k1 = *(const float4*)&sK[cur][s][f0 + 4];
            float4 q0 = *(const float4*)&sQ[cur][s][f0];
            float4 q1 = *(const float4*)&sQ[cur][s][f0 + 4];
            float vv = sV[cur][s][dl];
            float ev[8], kv[8], qv[8];
            *(float4*)&ev[0] = e0; *(float4*)&ev[4] = e1;
            *(float4*)&kv[0] = k0; *(float4*)&kv[4] = k1;
            *(float4*)&qv[0] = q0; *(float4*)&qv[4] = q1;
            float o = 0.f;
#pragma unroll
            for (int j = 0; j < 8; j++) {
                S[j] = fmaf(ev[j], S[j], kv[j] * vv);
                o = fmaf(qv[j], S[j], o);
            }
            sO[(s * 8 + dl) * 17 + fg] = o;
        }
        __syncthreads();

        if (tid < 64) {
            const int tt = tid >> 3, dd = tid & 7;
            float acc = 0.f;
#pragma unroll
            for (int g2 = 0; g2 < 16; g2++) acc += sO[(tt * 8 + dd) * 17 + g2];
            const int trow = blk * 8 + tt;
            g_o[((size_t)(b * T_LEN + trow)) * DMODEL + h * DFH + d0 + dd] = acc;
        }
    }
}

// =====================================================================
// fused RMSNorm + gw scale + bf16 hi/lo split of o  (block per row)
// =====================================================================
__global__ void rms_split_kernel(const float* __restrict__ gw)
{
    __shared__ float red[8];
    __shared__ float s_inv;
    const int row = blockIdx.x;
    const int tid = threadIdx.x;   // 256
    const float4 v = ((const float4*)(g_o + (size_t)row * DMODEL))[tid];
    float s = v.x * v.x + v.y * v.y + v.z * v.z + v.w * v.w;
#pragma unroll
    for (int o = 16; o > 0; o >>= 1) s += __shfl_xor_sync(0xffffffffu, s, o);
    if ((tid & 31) == 0) red[tid >> 5] = s;
    __syncthreads();
    if (tid == 0) {
        float t = 0.f;
#pragma unroll
        for (int w = 0; w < 8; w++) t += red[w];
        s_inv = rsqrtf(t * (1.0f / DMODEL) + 1e-5f);
    }
    __syncthreads();
    const float iv = s_inv;
    const float4 g4 = ((const float4*)gw)[tid];
    float a0 = v.x * iv * g4.x, a1 = v.y * iv * g4.y;
    float a2 = v.z * iv * g4.z, a3 = v.w * iv * g4.w;
    __nv_bfloat16 h0 = __float2bfloat16(a0);
    __nv_bfloat16 h1 = __float2bfloat16(a1);
    __nv_bfloat16 h2 = __float2bfloat16(a2);
    __nv_bfloat16 h3 = __float2bfloat16(a3);
    __nv_bfloat16 l0 = __float2bfloat16(a0 - __bfloat162float(h0));
    __nv_bfloat16 l1 = __float2bfloat16(a1 - __bfloat162float(h1));
    __nv_bfloat16 l2 = __float2bfloat16(a2 - __bfloat162float(h2));
    __nv_bfloat16 l3 = __float2bfloat16(a3 - __bfloat162float(h3));
    __nv_bfloat162* ph = (__nv_bfloat162*)(g_oh + (size_t)row * DMODEL) + tid * 2;
    __nv_bfloat162* pl = (__nv_bfloat162*)(g_ol + (size_t)row * DMODEL) + tid * 2;
    ph[0] = __nv_bfloat162(h0, h1); ph[1] = __nv_bfloat162(h2, h3);
    pl[0] = __nv_bfloat162(l0, l1); pl[1] = __nv_bfloat162(l2, l3);
}

// =====================================================================
extern "C" void kernel_launch(void* const* d_in, const int* in_sizes, int n_in,
                              void* d_out, int out_size)
{
    const float* x  = (const float*)d_in[0];
    const float* Wq = (const float*)d_in[1];
    const float* Wf = (const float*)d_in[2];
    const float* Wi = (const float*)d_in[3];
    const float* gw = (const float*)d_in[4];
    const float* Wo = (const float*)d_in[5];
    float* out = (float*)d_out;

    const int n4x = MROWS * DMODEL / 4;       // 2M
    const int n4w = DMODEL * DMODEL / 4;      // 256K
    split_kernel<<<n4x / 256, 256>>>(x,  0, 0, n4x);
    split_kernel<<<n4w / 256, 256>>>(Wq, 1, 0 * DMODEL * DMODEL, n4w);
    split_kernel<<<n4w / 256, 256>>>(Wf, 1, 1 * DMODEL * DMODEL, n4w);
    split_kernel<<<n4w / 256, 256>>>(Wi, 1, 2 * DMODEL * DMODEL, n4w);
    split_kernel<<<n4w / 256, 256>>>(Wo, 2, 0, n4w);

    gemm_bf3<0><<<dim3(24, 64), 256>>>(nullptr);
    recur_kernel<<<dim3(16, 16), 128>>>();
    rms_split_kernel<<<MROWS, 256>>>(gw);
    gemm_bf3<1><<<dim3(8, 64), 256>>>(out);
}

// round 5
// speedup vs baseline: 1.8898x; 1.1783x over previous
#include <cuda_runtime.h>
#include <cuda_bf16.h>
#include <cstdint>
#include <cstdio>

// Problem constants
#define T_LEN 4096
#define BATCH 2
#define DMODEL 1024
#define NH 8
#define DFH 128
#define DIH 128
#define BH (BATCH*NH)
#define MROWS (BATCH*T_LEN)

// ---------------- scratch (device globals; no runtime allocation) ----------------
__device__ float g_q[BH*T_LEN*DFH];   // silu(xWq^T) * DF^-0.5, layout [bh][t][f]
__device__ float g_e[BH*T_LEN*DFH];   // sigmoid(xWf^T); k = 1-e recomputed on the fly
__device__ float g_v[BH*T_LEN*DIH];   // xWi^T
__device__ float g_o[(size_t)MROWS*DMODEL];

// bf16 hi/lo split operands
__device__ __nv_bfloat16 g_xh[(size_t)MROWS*DMODEL];
__device__ __nv_bfloat16 g_xl[(size_t)MROWS*DMODEL];
__device__ __nv_bfloat16 g_wh[(size_t)3*DMODEL*DMODEL];
__device__ __nv_bfloat16 g_wl[(size_t)3*DMODEL*DMODEL];
__device__ __nv_bfloat16 g_oh[(size_t)MROWS*DMODEL];
__device__ __nv_bfloat16 g_ol[(size_t)MROWS*DMODEL];
__device__ __nv_bfloat16 g_woh[(size_t)DMODEL*DMODEL];
__device__ __nv_bfloat16 g_wol[(size_t)DMODEL*DMODEL];

// ---------------- helpers ----------------
__device__ __forceinline__ void cp16(void* s, const void* g) {
    uint32_t sa = (uint32_t)__cvta_generic_to_shared(s);
    asm volatile("cp.async.ca.shared.global [%0], [%1], 16;\n" :: "r"(sa), "l"(g));
}
__device__ __forceinline__ void cp16s(uint32_t sa, const void* g) {
    asm volatile("cp.async.ca.shared.global [%0], [%1], 16;\n" :: "r"(sa), "l"(g));
}
__device__ __forceinline__ uint32_t smem_u32(const void* p) {
    return (uint32_t)__cvta_generic_to_shared(p);
}

#define MMA_BF16(accp, A, B)                                                 \
    asm("mma.sync.aligned.m16n8k16.row.col.f32.bf16.bf16.f32 "               \
        "{%0,%1,%2,%3}, {%4,%5,%6,%7}, {%8,%9}, {%0,%1,%2,%3};"              \
        : "+f"((accp)[0]), "+f"((accp)[1]), "+f"((accp)[2]), "+f"((accp)[3]) \
        : "r"((A)[0]), "r"((A)[1]), "r"((A)[2]), "r"((A)[3]),                \
          "r"((B)[0]), "r"((B)[1]))

// =====================================================================
// split: fp32 -> (bf16 hi, bf16 lo).  dst_sel: 0=X, 1=W(off), 2=Wo
// =====================================================================
__global__ void split_kernel(const float* __restrict__ src, int dst_sel,
                             int off, int n4)
{
    int i = blockIdx.x * blockDim.x + threadIdx.x;
    if (i >= n4) return;
    __nv_bfloat16 *hi, *lo;
    if (dst_sel == 0)      { hi = g_xh;        lo = g_xl; }
    else if (dst_sel == 1) { hi = g_wh + off;  lo = g_wl + off; }
    else                   { hi = g_woh;       lo = g_wol; }

    float4 v = ((const float4*)src)[i];
    __nv_bfloat16 h0 = __float2bfloat16(v.x);
    __nv_bfloat16 h1 = __float2bfloat16(v.y);
    __nv_bfloat16 h2 = __float2bfloat16(v.z);
    __nv_bfloat16 h3 = __float2bfloat16(v.w);
    __nv_bfloat16 l0 = __float2bfloat16(v.x - __bfloat162float(h0));
    __nv_bfloat16 l1 = __float2bfloat16(v.y - __bfloat162float(h1));
    __nv_bfloat16 l2 = __float2bfloat16(v.z - __bfloat162float(h2));
    __nv_bfloat16 l3 = __float2bfloat16(v.w - __bfloat162float(h3));
    __nv_bfloat162* ph = (__nv_bfloat162*)(hi + (size_t)4 * i);
    __nv_bfloat162* pl = (__nv_bfloat162*)(lo + (size_t)4 * i);
    ph[0] = __nv_bfloat162(h0, h1); ph[1] = __nv_bfloat162(h2, h3);
    pl[0] = __nv_bfloat162(l0, l1); pl[1] = __nv_bfloat162(l2, l3);
}

// =====================================================================
// bf16x3 HMMA GEMM, 3-stage cp.async pipeline, 1 sync per K-step.
// CTA 128x128, BK=16, 8 warps (2x4) of 64x32.
// EPI=0: A=X, B=Wq|Wf|Wi, activation scatter.  EPI=1: A=o, B=Wo -> out.
// Dynamic smem: 3 stages x (Ah|Al|Bh|Bl), rows padded to 48B (conflict-free).
// =====================================================================
#define NSTG      3
#define STG_BYTES 24576
#define OFF_AL    6144
#define OFF_BH    12288
#define OFF_BL    18432
#define ROWB      48
#define SMEM_GEMM (NSTG * STG_BYTES)   // 73728

template<int EPI>
__global__ void __launch_bounds__(256, 2) gemm_mma(float* __restrict__ out)
{
    extern __shared__ char sm[];
    const uint32_t sb = smem_u32(sm);

    const __nv_bfloat16* __restrict__ Ahp = (EPI == 0) ? g_xh : g_oh;
    const __nv_bfloat16* __restrict__ Alp = (EPI == 0) ? g_xl : g_ol;
    const __nv_bfloat16* __restrict__ Bhp = (EPI == 0) ? g_wh : g_woh;
    const __nv_bfloat16* __restrict__ Blp = (EPI == 0) ? g_wl : g_wol;

    const int tid  = threadIdx.x;
    const int wid  = tid >> 5, lane = tid & 31;
    const int wm   = wid >> 2, wn = wid & 3;
    const int m0   = blockIdx.y * 128;
    const int n0   = blockIdx.x * 128;

    // staging map: each thread loads one 16B chunk per tensor
    const int srow = tid >> 1, sch = tid & 1;

    auto stage = [&](int stg, int kt) {
        const uint32_t dst = sb + stg * STG_BYTES + srow * ROWB + sch * 16;
        const size_t ao = (size_t)(m0 + srow) * 2048 + kt * 32 + sch * 16; // bytes
        const size_t bo = (size_t)(n0 + srow) * 2048 + kt * 32 + sch * 16;
        cp16s(dst,          (const char*)Ahp + ao);
        cp16s(dst + OFF_AL, (const char*)Alp + ao);
        cp16s(dst + OFF_BH, (const char*)Bhp + bo);
        cp16s(dst + OFF_BL, (const char*)Blp + bo);
    };

    float acc[4][4][4];
#pragma unroll
    for (int i = 0; i < 4; i++)
#pragma unroll
        for (int j = 0; j < 4; j++)
#pragma unroll
            for (int r = 0; r < 4; r++) acc[i][j][r] = 0.f;

    // ldmatrix lane geometry
    const int aRowOff = wm * 64 + ((lane >> 3) & 1) * 8 + (lane & 7);   // + mf*16
    const int aColB   = (lane >> 4) * 16;                                // byte offset
    const int grp     = lane >> 3;
    const int bRowOff = wn * 32 + (grp >> 1) * 8 + (lane & 7);           // + nfp*16
    const int bColB   = (grp & 1) * 16;

    stage(0, 0);
    asm volatile("cp.async.commit_group;\n");
    stage(1, 1);
    asm volatile("cp.async.commit_group;\n");

    const int NKT = DMODEL / 16;  // 64
    for (int kt = 0; kt < NKT; kt++) {
        if (kt < NKT - 1) asm volatile("cp.async.wait_group 1;\n");
        else              asm volatile("cp.async.wait_group 0;\n");
        __syncthreads();
        if (kt + 2 < NKT) {
            stage((kt + 2) % NSTG, kt + 2);
            asm volatile("cp.async.commit_group;\n");
        }

        const uint32_t tb = sb + (kt % NSTG) * STG_BYTES;

        uint32_t bh[4][2], bl[4][2];
#pragma unroll
        for (int nfp = 0; nfp < 2; nfp++) {
            uint32_t addr = tb + OFF_BH + (bRowOff + nfp * 16) * ROWB + bColB;
            asm volatile("ldmatrix.sync.aligned.m8n8.x4.shared.b16 {%0,%1,%2,%3}, [%4];"
                         : "=r"(bh[nfp*2][0]), "=r"(bh[nfp*2][1]),
                           "=r"(bh[nfp*2+1][0]), "=r"(bh[nfp*2+1][1]) : "r"(addr));
            uint32_t addr2 = tb + OFF_BL + (bRowOff + nfp * 16) * ROWB + bColB;
            asm volatile("ldmatrix.sync.aligned.m8n8.x4.shared.b16 {%0,%1,%2,%3}, [%4];"
                         : "=r"(bl[nfp*2][0]), "=r"(bl[nfp*2][1]),
                           "=r"(bl[nfp*2+1][0]), "=r"(bl[nfp*2+1][1]) : "r"(addr2));
        }
#pragma unroll
        for (int mf = 0; mf < 4; mf++) {
            uint32_t a[4], al2[4];
            uint32_t pa = tb + (aRowOff + mf * 16) * ROWB + aColB;
            asm volatile("ldmatrix.sync.aligned.m8n8.x4.shared.b16 {%0,%1,%2,%3}, [%4];"
                         : "=r"(a[0]), "=r"(a[1]), "=r"(a[2]), "=r"(a[3]) : "r"(pa));
            uint32_t pl = tb + OFF_AL + (aRowOff + mf * 16) * ROWB + aColB;
            asm volatile("ldmatrix.sync.aligned.m8n8.x4.shared.b16 {%0,%1,%2,%3}, [%4];"
                         : "=r"(al2[0]), "=r"(al2[1]), "=r"(al2[2]), "=r"(al2[3]) : "r"(pl));
#pragma unroll
            for (int nf = 0; nf < 4; nf++) MMA_BF16(acc[mf][nf], a,   bh[nf]);
#pragma unroll
            for (int nf = 0; nf < 4; nf++) MMA_BF16(acc[mf][nf], a,   bl[nf]);
#pragma unroll
            for (int nf = 0; nf < 4; nf++) MMA_BF16(acc[mf][nf], al2, bh[nf]);
        }
    }

    // epilogue
    const int g = lane >> 2, tg = lane & 3;
    if (EPI == 0) {
        const int mat = blockIdx.x >> 3;
        const int h   = blockIdx.x & 7;
        const float qscale = 0.08838834764831845f; // 128^-0.5
#pragma unroll
        for (int mf = 0; mf < 4; mf++)
#pragma unroll
        for (int nf = 0; nf < 4; nf++)
#pragma unroll
        for (int half = 0; half < 2; half++) {
            int m = m0 + wm * 64 + mf * 16 + g + half * 8;
            int f = wn * 32 + nf * 8 + tg * 2;
            int b = m >> 12, t = m & (T_LEN - 1);
            size_t base = (((size_t)(b * NH + h)) * T_LEN + t) * DFH + f;
            float y0 = acc[mf][nf][half * 2 + 0];
            float y1 = acc[mf][nf][half * 2 + 1];
            if (mat == 0) {
                float s0 = 1.f / (1.f + expf(-y0));
                float s1 = 1.f / (1.f + expf(-y1));
                *(float2*)(g_q + base) = make_float2(y0 * s0 * qscale, y1 * s1 * qscale);
            } else if (mat == 1) {
                float a0 = 1.f / (1.f + expf(-y0));
                float a1 = 1.f / (1.f + expf(-y1));
                *(float2*)(g_e + base) = make_float2(a0, a1);
            } else {
                *(float2*)(g_v + base) = make_float2(y0, y1);
            }
        }
    } else {
#pragma unroll
        for (int mf = 0; mf < 4; mf++)
#pragma unroll
        for (int nf = 0; nf < 4; nf++)
#pragma unroll
        for (int half = 0; half < 2; half++) {
            int m = m0 + wm * 64 + mf * 16 + g + half * 8;
            int n = n0 + wn * 32 + nf * 8 + tg * 2;
            *(float2*)(out + (size_t)m * DMODEL + n) =
                make_float2(acc[mf][nf][half * 2 + 0], acc[mf][nf][half * 2 + 1]);
        }
    }
}

// =====================================================================
// recurrence v2.  grid (8 dchunks, 16 bh), 128 threads.
// thread owns [8f x 2d] state; k = 1-e recomputed (g_k eliminated).
// cp.async double-buffered staging of 8 timesteps of e/q/v.
// =====================================================================
__global__ void __launch_bounds__(128) recur_kernel()
{
    __shared__ float sE[2][8][128];
    __shared__ float sQ[2][8][128];
    __shared__ float sV[2][8][16];
    __shared__ float sO[8 * 16 * 17];

    const int tid    = threadIdx.x;
    const int dchunk = blockIdx.x;   // 0..7
    const int bh     = blockIdx.y;   // 0..15
    const int d0 = dchunk * 16;
    const int fg = tid >> 3, dl = tid & 7, f0 = fg * 8;
    const int b = bh >> 3, h = bh & 7;
    const size_t bhbase = (size_t)bh * T_LEN * DFH;

    float S[16];
#pragma unroll
    for (int j = 0; j < 16; j++) S[j] = 0.f;

    auto stage = [&](int buf, int t0) {
#pragma unroll
        for (int p = 0; p < 2; p++) {
            int c = tid + p * 128;
            int s = c >> 5;
            int off = (c & 31) * 4;
            size_t gi = bhbase + (size_t)(t0 + s) * DFH + off;
            cp16(&sE[buf][s][off], g_e + gi);
            cp16(&sQ[buf][s][off], g_q + gi);
        }
        if (tid < 32) {
            int s = tid >> 2, off = (tid & 3) * 4;
            cp16(&sV[buf][s][off], g_v + bhbase + (size_t)(t0 + s) * DIH + d0 + off);
        }
    };

    stage(0, 0);
    asm volatile("cp.async.commit_group;\n");

    const int NBLK = T_LEN / 8;  // 512
    for (int blk = 0; blk < NBLK; blk++) {
        if (blk + 1 < NBLK) {
            stage((blk + 1) & 1, (blk + 1) * 8);
            asm volatile("cp.async.commit_group;\n");
            asm volatile("cp.async.wait_group 1;\n");
        } else {
            asm volatile("cp.async.wait_group 0;\n");
        }
        __syncthreads();

        const int cur = blk & 1;
#pragma unroll
        for (int s = 0; s < 8; s++) {
            float4 e0 = *(const float4*)&sE[cur][s][f0];
            float4 e1 = *(const float4*)&sE[cur][s][f0 + 4];
            float4 q0 = *(const float4*)&sQ[cur][s][f0];
            float4 q1 = *(const float4*)&sQ[cur][s][f0 + 4];
            float2 vv = *(const float2*)&sV[cur][s][dl * 2];
            float ev[8], qv[8];
            *(float4*)&ev[0] = e0; *(float4*)&ev[4] = e1;
            *(float4*)&qv[0] = q0; *(float4*)&qv[4] = q1;
            float o0 = 0.f, o1 = 0.f;
#pragma unroll
            for (int j = 0; j < 8; j++) {
                float kj = 1.f - ev[j];
                float t0 = kj * vv.x;
                float t1 = kj * vv.y;
                S[j * 2]     = fmaf(ev[j], S[j * 2],     t0);
                S[j * 2 + 1] = fmaf(ev[j], S[j * 2 + 1], t1);
                o0 = fmaf(qv[j], S[j * 2],     o0);
                o1 = fmaf(qv[j], S[j * 2 + 1], o1);
            }
            sO[(s * 16 + dl * 2 + 0) * 17 + fg] = o0;
            sO[(s * 16 + dl * 2 + 1) * 17 + fg] = o1;
        }
        __syncthreads();

        {
            const int tt = tid >> 4, dd = tid & 15;
            float acc = 0.f;
#pragma unroll
            for (int g2 = 0; g2 < 16; g2++) acc += sO[(tt * 16 + dd) * 17 + g2];
            const int trow = blk * 8 + tt;
            g_o[((size_t)(b * T_LEN + trow)) * DMODEL + h * DFH + d0 + dd] = acc;
        }
    }
}

// =====================================================================
// fused RMSNorm + gw scale + bf16 hi/lo split of o
// =====================================================================
__global__ void rms_split_kernel(const float* __restrict__ gw)
{
    __shared__ float red[8];
    __shared__ float s_inv;
    const int row = blockIdx.x;
    const int tid = threadIdx.x;   // 256
    const float4 v = ((const float4*)(g_o + (size_t)row * DMODEL))[tid];
    float s = v.x * v.x + v.y * v.y + v.z * v.z + v.w * v.w;
#pragma unroll
    for (int o = 16; o > 0; o >>= 1) s += __shfl_xor_sync(0xffffffffu, s, o);
    if ((tid & 31) == 0) red[tid >> 5] = s;
    __syncthreads();
    if (tid == 0) {
        float t = 0.f;
#pragma unroll
        for (int w = 0; w < 8; w++) t += red[w];
        s_inv = rsqrtf(t * (1.0f / DMODEL) + 1e-5f);
    }
    __syncthreads();
    const float iv = s_inv;
    const float4 g4 = ((const float4*)gw)[tid];
    float a0 = v.x * iv * g4.x, a1 = v.y * iv * g4.y;
    float a2 = v.z * iv * g4.z, a3 = v.w * iv * g4.w;
    __nv_bfloat16 h0 = __float2bfloat16(a0);
    __nv_bfloat16 h1 = __float2bfloat16(a1);
    __nv_bfloat16 h2 = __float2bfloat16(a2);
    __nv_bfloat16 h3 = __float2bfloat16(a3);
    __nv_bfloat16 l0 = __float2bfloat16(a0 - __bfloat162float(h0));
    __nv_bfloat16 l1 = __float2bfloat16(a1 - __bfloat162float(h1));
    __nv_bfloat16 l2 = __float2bfloat16(a2 - __bfloat162float(h2));
    __nv_bfloat16 l3 = __float2bfloat16(a3 - __bfloat162float(h3));
    __nv_bfloat162* ph = (__nv_bfloat162*)(g_oh + (size_t)row * DMODEL) + tid * 2;
    __nv_bfloat162* pl = (__nv_bfloat162*)(g_ol + (size_t)row * DMODEL) + tid * 2;
    ph[0] = __nv_bfloat162(h0, h1); ph[1] = __nv_bfloat162(h2, h3);
    pl[0] = __nv_bfloat162(l0, l1); pl[1] = __nv_bfloat162(l2, l3);
}

// =====================================================================
extern "C" void kernel_launch(void* const* d_in, const int* in_sizes, int n_in,
                              void* d_out, int out_size)
{
    const float* x  = (const float*)d_in[0];
    const float* Wq = (const float*)d_in[1];
    const float* Wf = (const float*)d_in[2];
    const float* Wi = (const float*)d_in[3];
    const float* gw = (const float*)d_in[4];
    const float* Wo = (const float*)d_in[5];
    float* out = (float*)d_out;

    cudaFuncSetAttribute(gemm_mma<0>, cudaFuncAttributeMaxDynamicSharedMemorySize, SMEM_GEMM);
    cudaFuncSetAttribute(gemm_mma<1>, cudaFuncAttributeMaxDynamicSharedMemorySize, SMEM_GEMM);

    const int n4x = MROWS * DMODEL / 4;
    const int n4w = DMODEL * DMODEL / 4;
    split_kernel<<<n4x / 256, 256>>>(x,  0, 0, n4x);
    split_kernel<<<n4w / 256, 256>>>(Wq, 1, 0 * DMODEL * DMODEL, n4w);
    split_kernel<<<n4w / 256, 256>>>(Wf, 1, 1 * DMODEL * DMODEL, n4w);
    split_kernel<<<n4w / 256, 256>>>(Wi, 1, 2 * DMODEL * DMODEL, n4w);
    split_kernel<<<n4w / 256, 256>>>(Wo, 2, 0, n4w);

    gemm_mma<0><<<dim3(24, 64), 256, SMEM_GEMM>>>(nullptr);
    recur_kernel<<<dim3(8, 16), 128>>>();
    rms_split_kernel<<<MROWS, 256>>>(gw);
    gemm_mma<1><<<dim3(8, 64), 256, SMEM_GEMM>>>(out);
}

// round 6
// speedup vs baseline: 2.2569x; 1.1942x over previous
#include <cuda_runtime.h>
#include <cuda_bf16.h>
#include <cuda_fp16.h>
#include <cstdint>
#include <cstdio>

// Problem constants
#define T_LEN 4096
#define BATCH 2
#define DMODEL 1024
#define NH 8
#define DFH 128
#define DIH 128
#define BH (BATCH*NH)
#define MROWS (BATCH*T_LEN)

// ---------------- scratch (device globals; no runtime allocation) ----------------
__device__ float g_q[BH*T_LEN*DFH];   // silu(xWq^T) * DF^-0.5, layout [bh][t][f]
__device__ float g_e[BH*T_LEN*DFH];   // sigmoid(xWf^T); k = 1-e recomputed on the fly
__device__ float g_v[BH*T_LEN*DIH];   // xWi^T
__device__ float g_o[(size_t)MROWS*DMODEL];

// fp16 operands: activations split hi+lo (exact to 2^-22), weights rounded once
__device__ __half g_xh[(size_t)MROWS*DMODEL];
__device__ __half g_xl[(size_t)MROWS*DMODEL];
__device__ __half g_w16[(size_t)3*DMODEL*DMODEL];   // Wq|Wf|Wi rows
__device__ __half g_oh[(size_t)MROWS*DMODEL];
__device__ __half g_ol[(size_t)MROWS*DMODEL];
__device__ __half g_wo16[(size_t)DMODEL*DMODEL];

// ---------------- helpers ----------------
__device__ __forceinline__ void cp16(void* s, const void* g) {
    uint32_t sa = (uint32_t)__cvta_generic_to_shared(s);
    asm volatile("cp.async.ca.shared.global [%0], [%1], 16;\n" :: "r"(sa), "l"(g));
}
__device__ __forceinline__ void cp16s(uint32_t sa, const void* g) {
    asm volatile("cp.async.ca.shared.global [%0], [%1], 16;\n" :: "r"(sa), "l"(g));
}
__device__ __forceinline__ uint32_t smem_u32(const void* p) {
    return (uint32_t)__cvta_generic_to_shared(p);
}

#define MMA_F16(accp, A, B)                                                  \
    asm("mma.sync.aligned.m16n8k16.row.col.f32.f16.f16.f32 "                 \
        "{%0,%1,%2,%3}, {%4,%5,%6,%7}, {%8,%9}, {%0,%1,%2,%3};"              \
        : "+f"((accp)[0]), "+f"((accp)[1]), "+f"((accp)[2]), "+f"((accp)[3]) \
        : "r"((A)[0]), "r"((A)[1]), "r"((A)[2]), "r"((A)[3]),                \
          "r"((B)[0]), "r"((B)[1]))

// =====================================================================
// split2: fp32 activations -> (fp16 hi, fp16 lo).  dst_sel: 0=X, 1=o (unused here)
// round1: fp32 weights -> fp16 (single)
// =====================================================================
__global__ void split2_kernel(const float* __restrict__ src, int n4)
{
    int i = blockIdx.x * blockDim.x + threadIdx.x;
    if (i >= n4) return;
    float4 v = ((const float4*)src)[i];
    __half h0 = __float2half_rn(v.x);
    __half h1 = __float2half_rn(v.y);
    __half h2 = __float2half_rn(v.z);
    __half h3 = __float2half_rn(v.w);
    __half l0 = __float2half_rn(v.x - __half2float(h0));
    __half l1 = __float2half_rn(v.y - __half2float(h1));
    __half l2 = __float2half_rn(v.z - __half2float(h2));
    __half l3 = __float2half_rn(v.w - __half2float(h3));
    __half2* ph = (__half2*)(g_xh + (size_t)4 * i);
    __half2* pl = (__half2*)(g_xl + (size_t)4 * i);
    ph[0] = __halves2half2(h0, h1); ph[1] = __halves2half2(h2, h3);
    pl[0] = __halves2half2(l0, l1); pl[1] = __halves2half2(l2, l3);
}

__global__ void round1_kernel(const float* __restrict__ src, int dst_sel,
                              int off, int n4)
{
    int i = blockIdx.x * blockDim.x + threadIdx.x;
    if (i >= n4) return;
    __half* dst = (dst_sel == 0) ? (g_w16 + off) : g_wo16;
    float4 v = ((const float4*)src)[i];
    __half2* p = (__half2*)(dst + (size_t)4 * i);
    p[0] = __halves2half2(__float2half_rn(v.x), __float2half_rn(v.y));
    p[1] = __halves2half2(__float2half_rn(v.z), __float2half_rn(v.w));
}

// =====================================================================
// fp16x2 HMMA GEMM: C = (Ah+Al) @ Bh^T, fp32 acc.  2 MMA terms.
// CTA 128x128, BK=16, 8 warps (2x4) of 64x32, 3-stage cp.async, 1 sync/K-step.
// EPI=0: A=X, B=Wq|Wf|Wi, activation scatter.  EPI=1: A=o, B=Wo -> out.
// =====================================================================
#define NSTG      3
#define STG_BYTES 18432
#define OFF_AL    6144
#define OFF_BH    12288
#define ROWB      48
#define SMEM_GEMM (NSTG * STG_BYTES)   // 55296

template<int EPI>
__global__ void __launch_bounds__(256, 2) gemm_mma(float* __restrict__ out)
{
    extern __shared__ char sm[];
    const uint32_t sb = smem_u32(sm);

    const __half* __restrict__ Ahp = (EPI == 0) ? g_xh : g_oh;
    const __half* __restrict__ Alp = (EPI == 0) ? g_xl : g_ol;
    const __half* __restrict__ Bhp = (EPI == 0) ? g_w16 : g_wo16;

    const int tid  = threadIdx.x;
    const int wid  = tid >> 5, lane = tid & 31;
    const int wm   = wid >> 2, wn = wid & 3;
    const int m0   = blockIdx.y * 128;
    const int n0   = blockIdx.x * 128;

    const int srow = tid >> 1, sch = tid & 1;

    auto stage = [&](int stg, int kt) {
        const uint32_t dst = sb + stg * STG_BYTES + srow * ROWB + sch * 16;
        const size_t ao = (size_t)(m0 + srow) * 2048 + kt * 32 + sch * 16; // bytes
        const size_t bo = (size_t)(n0 + srow) * 2048 + kt * 32 + sch * 16;
        cp16s(dst,          (const char*)Ahp + ao);
        cp16s(dst + OFF_AL, (const char*)Alp + ao);
        cp16s(dst + OFF_BH, (const char*)Bhp + bo);
    };

    float acc[4][4][4];
#pragma unroll
    for (int i = 0; i < 4; i++)
#pragma unroll
        for (int j = 0; j < 4; j++)
#pragma unroll
            for (int r = 0; r < 4; r++) acc[i][j][r] = 0.f;

    // ldmatrix lane geometry
    const int aRowOff = wm * 64 + ((lane >> 3) & 1) * 8 + (lane & 7);   // + mf*16
    const int aColB   = (lane >> 4) * 16;                                // byte offset
    const int grp     = lane >> 3;
    const int bRowOff = wn * 32 + (grp >> 1) * 8 + (lane & 7);           // + nfp*16
    const int bColB   = (grp & 1) * 16;

    stage(0, 0);
    asm volatile("cp.async.commit_group;\n");
    stage(1, 1);
    asm volatile("cp.async.commit_group;\n");

    const int NKT = DMODEL / 16;  // 64
    for (int kt = 0; kt < NKT; kt++) {
        if (kt < NKT - 1) asm volatile("cp.async.wait_group 1;\n");
        else              asm volatile("cp.async.wait_group 0;\n");
        __syncthreads();
        if (kt + 2 < NKT) {
            stage((kt + 2) % NSTG, kt + 2);
            asm volatile("cp.async.commit_group;\n");
        }

        const uint32_t tb = sb + (kt % NSTG) * STG_BYTES;

        uint32_t bh[4][2];
#pragma unroll
        for (int nfp = 0; nfp < 2; nfp++) {
            uint32_t addr = tb + OFF_BH + (bRowOff + nfp * 16) * ROWB + bColB;
            asm volatile("ldmatrix.sync.aligned.m8n8.x4.shared.b16 {%0,%1,%2,%3}, [%4];"
                         : "=r"(bh[nfp*2][0]), "=r"(bh[nfp*2][1]),
                           "=r"(bh[nfp*2+1][0]), "=r"(bh[nfp*2+1][1]) : "r"(addr));
        }
#pragma unroll
        for (int mf = 0; mf < 4; mf++) {
            uint32_t a[4], al2[4];
            uint32_t pa = tb + (aRowOff + mf * 16) * ROWB + aColB;
            asm volatile("ldmatrix.sync.aligned.m8n8.x4.shared.b16 {%0,%1,%2,%3}, [%4];"
                         : "=r"(a[0]), "=r"(a[1]), "=r"(a[2]), "=r"(a[3]) : "r"(pa));
            uint32_t pl = tb + OFF_AL + (aRowOff + mf * 16) * ROWB + aColB;
            asm volatile("ldmatrix.sync.aligned.m8n8.x4.shared.b16 {%0,%1,%2,%3}, [%4];"
                         : "=r"(al2[0]), "=r"(al2[1]), "=r"(al2[2]), "=r"(al2[3]) : "r"(pl));
#pragma unroll
            for (int nf = 0; nf < 4; nf++) MMA_F16(acc[mf][nf], a,   bh[nf]);
#pragma unroll
            for (int nf = 0; nf < 4; nf++) MMA_F16(acc[mf][nf], al2, bh[nf]);
        }
    }

    // epilogue
    const int g = lane >> 2, tg = lane & 3;
    if (EPI == 0) {
        const int mat = blockIdx.x >> 3;
        const int h   = blockIdx.x & 7;
        const float qscale = 0.08838834764831845f; // 128^-0.5
#pragma unroll
        for (int mf = 0; mf < 4; mf++)
#pragma unroll
        for (int nf = 0; nf < 4; nf++)
#pragma unroll
        for (int half = 0; half < 2; half++) {
            int m = m0 + wm * 64 + mf * 16 + g + half * 8;
            int f = wn * 32 + nf * 8 + tg * 2;
            int b = m >> 12, t = m & (T_LEN - 1);
            size_t base = (((size_t)(b * NH + h)) * T_LEN + t) * DFH + f;
            float y0 = acc[mf][nf][half * 2 + 0];
            float y1 = acc[mf][nf][half * 2 + 1];
            if (mat == 0) {
                float s0 = 1.f / (1.f + expf(-y0));
                float s1 = 1.f / (1.f + expf(-y1));
                *(float2*)(g_q + base) = make_float2(y0 * s0 * qscale, y1 * s1 * qscale);
            } else if (mat == 1) {
                float a0 = 1.f / (1.f + expf(-y0));
                float a1 = 1.f / (1.f + expf(-y1));
                *(float2*)(g_e + base) = make_float2(a0, a1);
            } else {
                *(float2*)(g_v + base) = make_float2(y0, y1);
            }
        }
    } else {
#pragma unroll
        for (int mf = 0; mf < 4; mf++)
#pragma unroll
        for (int nf = 0; nf < 4; nf++)
#pragma unroll
        for (int half = 0; half < 2; half++) {
            int m = m0 + wm * 64 + mf * 16 + g + half * 8;
            int n = n0 + wn * 32 + nf * 8 + tg * 2;
            *(float2*)(out + (size_t)m * DMODEL + n) =
                make_float2(acc[mf][nf][half * 2 + 0], acc[mf][nf][half * 2 + 1]);
        }
    }
}

// =====================================================================
// recurrence.  grid (8 dchunks, 16 bh), 128 threads.
// thread owns [8f x 2d] state; k = 1-e recomputed.
// =====================================================================
__global__ void __launch_bounds__(128) recur_kernel()
{
    __shared__ float sE[2][8][128];
    __shared__ float sQ[2][8][128];
    __shared__ float sV[2][8][16];
    __shared__ float sO[8 * 16 * 17];

    const int tid    = threadIdx.x;
    const int dchunk = blockIdx.x;   // 0..7
    const int bh     = blockIdx.y;   // 0..15
    const int d0 = dchunk * 16;
    const int fg = tid >> 3, dl = tid & 7, f0 = fg * 8;
    const int b = bh >> 3, h = bh & 7;
    const size_t bhbase = (size_t)bh * T_LEN * DFH;

    float S[16];
#pragma unroll
    for (int j = 0; j < 16; j++) S[j] = 0.f;

    auto stage = [&](int buf, int t0) {
#pragma unroll
        for (int p = 0; p < 2; p++) {
            int c = tid + p * 128;
            int s = c >> 5;
            int off = (c & 31) * 4;
            size_t gi = bhbase + (size_t)(t0 + s) * DFH + off;
            cp16(&sE[buf][s][off], g_e + gi);
            cp16(&sQ[buf][s][off], g_q + gi);
        }
        if (tid < 32) {
            int s = tid >> 2, off = (tid & 3) * 4;
            cp16(&sV[buf][s][off], g_v + bhbase + (size_t)(t0 + s) * DIH + d0 + off);
        }
    };

    stage(0, 0);
    asm volatile("cp.async.commit_group;\n");

    const int NBLK = T_LEN / 8;  // 512
    for (int blk = 0; blk < NBLK; blk++) {
        if (blk + 1 < NBLK) {
            stage((blk + 1) & 1, (blk + 1) * 8);
            asm volatile("cp.async.commit_group;\n");
            asm volatile("cp.async.wait_group 1;\n");
        } else {
            asm volatile("cp.async.wait_group 0;\n");
        }
        __syncthreads();

        const int cur = blk & 1;
#pragma unroll
        for (int s = 0; s < 8; s++) {
            float4 e0 = *(const float4*)&sE[cur][s][f0];
            float4 e1 = *(const float4*)&sE[cur][s][f0 + 4];
            float4 q0 = *(const float4*)&sQ[cur][s][f0];
            float4 q1 = *(const float4*)&sQ[cur][s][f0 + 4];
            float2 vv = *(const float2*)&sV[cur][s][dl * 2];
            float ev[8], qv[8];
            *(float4*)&ev[0] = e0; *(float4*)&ev[4] = e1;
            *(float4*)&qv[0] = q0; *(float4*)&qv[4] = q1;
            float o0 = 0.f, o1 = 0.f;
#pragma unroll
            for (int j = 0; j < 8; j++) {
                float kj = 1.f - ev[j];
                float t0 = kj * vv.x;
                float t1 = kj * vv.y;
                S[j * 2]     = fmaf(ev[j], S[j * 2],     t0);
                S[j * 2 + 1] = fmaf(ev[j], S[j * 2 + 1], t1);
                o0 = fmaf(qv[j], S[j * 2],     o0);
                o1 = fmaf(qv[j], S[j * 2 + 1], o1);
            }
            sO[(s * 16 + dl * 2 + 0) * 17 + fg] = o0;
            sO[(s * 16 + dl * 2 + 1) * 17 + fg] = o1;
        }
        __syncthreads();

        {
            const int tt = tid >> 4, dd = tid & 15;
            float acc = 0.f;
#pragma unroll
            for (int g2 = 0; g2 < 16; g2++) acc += sO[(tt * 16 + dd) * 17 + g2];
            const int trow = blk * 8 + tt;
            g_o[((size_t)(b * T_LEN + trow)) * DMODEL + h * DFH + d0 + dd] = acc;
        }
    }
}

// =====================================================================
// fused RMSNorm + gw scale + fp16 hi/lo split of o
// =====================================================================
__global__ void rms_split_kernel(const float* __restrict__ gw)
{
    __shared__ float red[8];
    __shared__ float s_inv;
    const int row = blockIdx.x;
    const int tid = threadIdx.x;   // 256
    const float4 v = ((const float4*)(g_o + (size_t)row * DMODEL))[tid];
    float s = v.x * v.x + v.y * v.y + v.z * v.z + v.w * v.w;
#pragma unroll
    for (int o = 16; o > 0; o >>= 1) s += __shfl_xor_sync(0xffffffffu, s, o);
    if ((tid & 31) == 0) red[tid >> 5] = s;
    __syncthreads();
    if (tid == 0) {
        float t = 0.f;
#pragma unroll
        for (int w = 0; w < 8; w++) t += red[w];
        s_inv = rsqrtf(t * (1.0f / DMODEL) + 1e-5f);
    }
    __syncthreads();
    const float iv = s_inv;
    const float4 g4 = ((const float4*)gw)[tid];
    float a0 = v.x * iv * g4.x, a1 = v.y * iv * g4.y;
    float a2 = v.z * iv * g4.z, a3 = v.w * iv * g4.w;
    __half h0 = __float2half_rn(a0);
    __half h1 = __float2half_rn(a1);
    __half h2 = __float2half_rn(a2);
    __half h3 = __float2half_rn(a3);
    __half l0 = __float2half_rn(a0 - __half2float(h0));
    __half l1 = __float2half_rn(a1 - __half2float(h1));
    __half l2 = __float2half_rn(a2 - __half2float(h2));
    __half l3 = __float2half_rn(a3 - __half2float(h3));
    __half2* ph = (__half2*)(g_oh + (size_t)row * DMODEL) + tid * 2;
    __half2* pl = (__half2*)(g_ol + (size_t)row * DMODEL) + tid * 2;
    ph[0] = __halves2half2(h0, h1); ph[1] = __halves2half2(h2, h3);
    pl[0] = __halves2half2(l0, l1); pl[1] = __halves2half2(l2, l3);
}

// =====================================================================
extern "C" void kernel_launch(void* const* d_in, const int* in_sizes, int n_in,
                              void* d_out, int out_size)
{
    const float* x  = (const float*)d_in[0];
    const float* Wq = (const float*)d_in[1];
    const float* Wf = (const float*)d_in[2];
    const float* Wi = (const float*)d_in[3];
    const float* gw = (const float*)d_in[4];
    const float* Wo = (const float*)d_in[5];
    float* out = (float*)d_out;

    cudaFuncSetAttribute(gemm_mma<0>, cudaFuncAttributeMaxDynamicSharedMemorySize, SMEM_GEMM);
    cudaFuncSetAttribute(gemm_mma<1>, cudaFuncAttributeMaxDynamicSharedMemorySize, SMEM_GEMM);

    const int n4x = MROWS * DMODEL / 4;
    const int n4w = DMODEL * DMODEL / 4;
    split2_kernel<<<n4x / 256, 256>>>(x, n4x);
    round1_kernel<<<n4w / 256, 256>>>(Wq, 0, 0 * DMODEL * DMODEL, n4w);
    round1_kernel<<<n4w / 256, 256>>>(Wf, 0, 1 * DMODEL * DMODEL, n4w);
    round1_kernel<<<n4w / 256, 256>>>(Wi, 0, 2 * DMODEL * DMODEL, n4w);
    round1_kernel<<<n4w / 256, 256>>>(Wo, 1, 0, n4w);

    gemm_mma<0><<<dim3(24, 64), 256, SMEM_GEMM>>>(nullptr);
    recur_kernel<<<dim3(8, 16), 128>>>();
    rms_split_kernel<<<MROWS, 256>>>(gw);
    gemm_mma<1><<<dim3(8, 64), 256, SMEM_GEMM>>>(out);
}

// round 7
// speedup vs baseline: 2.9696x; 1.3158x over previous
#include <cuda_runtime.h>
#include <cuda_bf16.h>
#include <cuda_fp16.h>
#include <cstdint>
#include <cstdio>

// Problem constants
#define T_LEN 4096
#define BATCH 2
#define DMODEL 1024
#define NH 8
#define DFH 128
#define DIH 128
#define BH (BATCH*NH)
#define MROWS (BATCH*T_LEN)

// ---------------- scratch (device globals; no runtime allocation) ----------------
__device__ float g_q[BH*T_LEN*DFH];   // silu(xWq^T) * DF^-0.5, layout [bh][t][f]
__device__ float g_e[BH*T_LEN*DFH];   // sigmoid(xWf^T); k = 1-e recomputed on the fly
__device__ float g_v[BH*T_LEN*DIH];   // xWi^T
__device__ float g_o[(size_t)MROWS*DMODEL];

// fp16 operands (single-term round-to-nearest)
__device__ __half g_x16[(size_t)MROWS*DMODEL];
__device__ __half g_w16[(size_t)3*DMODEL*DMODEL];   // Wq|Wf|Wi rows
__device__ __half g_o16[(size_t)MROWS*DMODEL];
__device__ __half g_wo16[(size_t)DMODEL*DMODEL];

// ---------------- helpers ----------------
__device__ __forceinline__ void cp16(void* s, const void* g) {
    uint32_t sa = (uint32_t)__cvta_generic_to_shared(s);
    asm volatile("cp.async.ca.shared.global [%0], [%1], 16;\n" :: "r"(sa), "l"(g));
}
__device__ __forceinline__ void cp16s(uint32_t sa, const void* g) {
    asm volatile("cp.async.ca.shared.global [%0], [%1], 16;\n" :: "r"(sa), "l"(g));
}
__device__ __forceinline__ uint32_t smem_u32(const void* p) {
    return (uint32_t)__cvta_generic_to_shared(p);
}

#define MMA_F16(accp, A, B)                                                  \
    asm("mma.sync.aligned.m16n8k16.row.col.f32.f16.f16.f32 "                 \
        "{%0,%1,%2,%3}, {%4,%5,%6,%7}, {%8,%9}, {%0,%1,%2,%3};"              \
        : "+f"((accp)[0]), "+f"((accp)[1]), "+f"((accp)[2]), "+f"((accp)[3]) \
        : "r"((A)[0]), "r"((A)[1]), "r"((A)[2]), "r"((A)[3]),                \
          "r"((B)[0]), "r"((B)[1]))

// =====================================================================
// round: fp32 -> fp16.  dst_sel: 0=X, 1=W(off), 2=Wo
// =====================================================================
__global__ void round_kernel(const float* __restrict__ src, int dst_sel,
                             int off, int n4)
{
    int i = blockIdx.x * blockDim.x + threadIdx.x;
    if (i >= n4) return;
    __half* dst;
    if (dst_sel == 0)      dst = g_x16;
    else if (dst_sel == 1) dst = g_w16 + off;
    else                   dst = g_wo16;
    float4 v = ((const float4*)src)[i];
    __half2* p = (__half2*)(dst + (size_t)4 * i);
    p[0] = __halves2half2(__float2half_rn(v.x), __float2half_rn(v.y));
    p[1] = __halves2half2(__float2half_rn(v.z), __float2half_rn(v.w));
}

// =====================================================================
// fp16 HMMA GEMM: C = A16 @ B16^T, fp32 acc.  1 MMA term.
// CTA 128x128, BK=16, 8 warps (2x4) of 64x32, 3-stage cp.async, 1 sync/K-step.
// EPI=0: A=X, B=Wq|Wf|Wi, activation scatter.  EPI=1: A=o, B=Wo -> out.
// =====================================================================
#define NSTG      3
#define STG_BYTES 12288
#define OFF_B     6144
#define ROWB      48
#define SMEM_GEMM (NSTG * STG_BYTES)   // 36864

template<int EPI>
__global__ void __launch_bounds__(256, 2) gemm_mma(float* __restrict__ out)
{
    extern __shared__ char sm[];
    const uint32_t sb = smem_u32(sm);

    const __half* __restrict__ Ap = (EPI == 0) ? g_x16 : g_o16;
    const __half* __restrict__ Bp = (EPI == 0) ? g_w16 : g_wo16;

    const int tid  = threadIdx.x;
    const int wid  = tid >> 5, lane = tid & 31;
    const int wm   = wid >> 2, wn = wid & 3;
    const int m0   = blockIdx.y * 128;
    const int n0   = blockIdx.x * 128;

    const int srow = tid >> 1, sch = tid & 1;

    auto stage = [&](int stg, int kt) {
        const uint32_t dst = sb + stg * STG_BYTES + srow * ROWB + sch * 16;
        const size_t ao = (size_t)(m0 + srow) * 2048 + kt * 32 + sch * 16; // bytes
        const size_t bo = (size_t)(n0 + srow) * 2048 + kt * 32 + sch * 16;
        cp16s(dst,         (const char*)Ap + ao);
        cp16s(dst + OFF_B, (const char*)Bp + bo);
    };

    float acc[4][4][4];
#pragma unroll
    for (int i = 0; i < 4; i++)
#pragma unroll
        for (int j = 0; j < 4; j++)
#pragma unroll
            for (int r = 0; r < 4; r++) acc[i][j][r] = 0.f;

    // ldmatrix lane geometry
    const int aRowOff = wm * 64 + ((lane >> 3) & 1) * 8 + (lane & 7);   // + mf*16
    const int aColB   = (lane >> 4) * 16;                                // byte offset
    const int grp     = lane >> 3;
    const int bRowOff = wn * 32 + (grp >> 1) * 8 + (lane & 7);           // + nfp*16
    const int bColB   = (grp & 1) * 16;

    stage(0, 0);
    asm volatile("cp.async.commit_group;\n");
    stage(1, 1);
    asm volatile("cp.async.commit_group;\n");

    const int NKT = DMODEL / 16;  // 64
    for (int kt = 0; kt < NKT; kt++) {
        if (kt < NKT - 1) asm volatile("cp.async.wait_group 1;\n");
        else              asm volatile("cp.async.wait_group 0;\n");
        __syncthreads();
        if (kt + 2 < NKT) {
            stage((kt + 2) % NSTG, kt + 2);
            asm volatile("cp.async.commit_group;\n");
        }

        const uint32_t tb = sb + (kt % NSTG) * STG_BYTES;

        uint32_t bh[4][2];
#pragma unroll
        for (int nfp = 0; nfp < 2; nfp++) {
            uint32_t addr = tb + OFF_B + (bRowOff + nfp * 16) * ROWB + bColB;
            asm volatile("ldmatrix.sync.aligned.m8n8.x4.shared.b16 {%0,%1,%2,%3}, [%4];"
                         : "=r"(bh[nfp*2][0]), "=r"(bh[nfp*2][1]),
                           "=r"(bh[nfp*2+1][0]), "=r"(bh[nfp*2+1][1]) : "r"(addr));
        }
#pragma unroll
        for (int mf = 0; mf < 4; mf++) {
            uint32_t a[4];
            uint32_t pa = tb + (aRowOff + mf * 16) * ROWB + aColB;
            asm volatile("ldmatrix.sync.aligned.m8n8.x4.shared.b16 {%0,%1,%2,%3}, [%4];"
                         : "=r"(a[0]), "=r"(a[1]), "=r"(a[2]), "=r"(a[3]) : "r"(pa));
#pragma unroll
            for (int nf = 0; nf < 4; nf++) MMA_F16(acc[mf][nf], a, bh[nf]);
        }
    }

    // epilogue
    const int g = lane >> 2, tg = lane & 3;
    if (EPI == 0) {
        const int mat = blockIdx.x >> 3;
        const int h   = blockIdx.x & 7;
        const float qscale = 0.08838834764831845f; // 128^-0.5
#pragma unroll
        for (int mf = 0; mf < 4; mf++)
#pragma unroll
        for (int nf = 0; nf < 4; nf++)
#pragma unroll
        for (int half = 0; half < 2; half++) {
            int m = m0 + wm * 64 + mf * 16 + g + half * 8;
            int f = wn * 32 + nf * 8 + tg * 2;
            int b = m >> 12, t = m & (T_LEN - 1);
            size_t base = (((size_t)(b * NH + h)) * T_LEN + t) * DFH + f;
            float y0 = acc[mf][nf][half * 2 + 0];
            float y1 = acc[mf][nf][half * 2 + 1];
            if (mat == 0) {
                float s0 = 1.f / (1.f + expf(-y0));
                float s1 = 1.f / (1.f + expf(-y1));
                *(float2*)(g_q + base) = make_float2(y0 * s0 * qscale, y1 * s1 * qscale);
            } else if (mat == 1) {
                float a0 = 1.f / (1.f + expf(-y0));
                float a1 = 1.f / (1.f + expf(-y1));
                *(float2*)(g_e + base) = make_float2(a0, a1);
            } else {
                *(float2*)(g_v + base) = make_float2(y0, y1);
            }
        }
    } else {
#pragma unroll
        for (int mf = 0; mf < 4; mf++)
#pragma unroll
        for (int nf = 0; nf < 4; nf++)
#pragma unroll
        for (int half = 0; half < 2; half++) {
            int m = m0 + wm * 64 + mf * 16 + g + half * 8;
            int n = n0 + wn * 32 + nf * 8 + tg * 2;
            *(float2*)(out + (size_t)m * DMODEL + n) =
                make_float2(acc[mf][nf][half * 2 + 0], acc[mf][nf][half * 2 + 1]);
        }
    }
}

// =====================================================================
// recurrence.  grid (8 dchunks, 16 bh), 128 threads.
// thread owns [8f x 2d] state; k = 1-e recomputed.
// =====================================================================
__global__ void __launch_bounds__(128) recur_kernel()
{
    __shared__ float sE[2][8][128];
    __shared__ float sQ[2][8][128];
    __shared__ float sV[2][8][16];
    __shared__ float sO[8 * 16 * 17];

    const int tid    = threadIdx.x;
    const int dchunk = blockIdx.x;   // 0..7
    const int bh     = blockIdx.y;   // 0..15
    const int d0 = dchunk * 16;
    const int fg = tid >> 3, dl = tid & 7, f0 = fg * 8;
    const int b = bh >> 3, h = bh & 7;
    const size_t bhbase = (size_t)bh * T_LEN * DFH;

    float S[16];
#pragma unroll
    for (int j = 0; j < 16; j++) S[j] = 0.f;

    auto stage = [&](int buf, int t0) {
#pragma unroll
        for (int p = 0; p < 2; p++) {
            int c = tid + p * 128;
            int s = c >> 5;
            int off = (c & 31) * 4;
            size_t gi = bhbase + (size_t)(t0 + s) * DFH + off;
            cp16(&sE[buf][s][off], g_e + gi);
            cp16(&sQ[buf][s][off], g_q + gi);
        }
        if (tid < 32) {
            int s = tid >> 2, off = (tid & 3) * 4;
            cp16(&sV[buf][s][off], g_v + bhbase + (size_t)(t0 + s) * DIH + d0 + off);
        }
    };

    stage(0, 0);
    asm volatile("cp.async.commit_group;\n");

    const int NBLK = T_LEN / 8;  // 512
    for (int blk = 0; blk < NBLK; blk++) {
        if (blk + 1 < NBLK) {
            stage((blk + 1) & 1, (blk + 1) * 8);
            asm volatile("cp.async.commit_group;\n");
            asm volatile("cp.async.wait_group 1;\n");
        } else {
            asm volatile("cp.async.wait_group 0;\n");
        }
        __syncthreads();

        const int cur = blk & 1;
#pragma unroll
        for (int s = 0; s < 8; s++) {
            float4 e0 = *(const float4*)&sE[cur][s][f0];
            float4 e1 = *(const float4*)&sE[cur][s][f0 + 4];
            float4 q0 = *(const float4*)&sQ[cur][s][f0];
            float4 q1 = *(const float4*)&sQ[cur][s][f0 + 4];
            float2 vv = *(const float2*)&sV[cur][s][dl * 2];
            float ev[8], qv[8];
            *(float4*)&ev[0] = e0; *(float4*)&ev[4] = e1;
            *(float4*)&qv[0] = q0; *(float4*)&qv[4] = q1;
            float o0 = 0.f, o1 = 0.f;
#pragma unroll
            for (int j = 0; j < 8; j++) {
                float kj = 1.f - ev[j];
                float t0 = kj * vv.x;
                float t1 = kj * vv.y;
                S[j * 2]     = fmaf(ev[j], S[j * 2],     t0);
                S[j * 2 + 1] = fmaf(ev[j], S[j * 2 + 1], t1);
                o0 = fmaf(qv[j], S[j * 2],     o0);
                o1 = fmaf(qv[j], S[j * 2 + 1], o1);
            }
            sO[(s * 16 + dl * 2 + 0) * 17 + fg] = o0;
            sO[(s * 16 + dl * 2 + 1) * 17 + fg] = o1;
        }
        __syncthreads();

        {
            const int tt = tid >> 4, dd = tid & 15;
            float acc = 0.f;
#pragma unroll
            for (int g2 = 0; g2 < 16; g2++) acc += sO[(tt * 16 + dd) * 17 + g2];
            const int trow = blk * 8 + tt;
            g_o[((size_t)(b * T_LEN + trow)) * DMODEL + h * DFH + d0 + dd] = acc;
        }
    }
}

// =====================================================================
// fused RMSNorm + gw scale + fp16 round of o
// =====================================================================
__global__ void rms_round_kernel(const float* __restrict__ gw)
{
    __shared__ float red[8];
    __shared__ float s_inv;
    const int row = blockIdx.x;
    const int tid = threadIdx.x;   // 256
    const float4 v = ((const float4*)(g_o + (size_t)row * DMODEL))[tid];
    float s = v.x * v.x + v.y * v.y + v.z * v.z + v.w * v.w;
#pragma unroll
    for (int o = 16; o > 0; o >>= 1) s += __shfl_xor_sync(0xffffffffu, s, o);
    if ((tid & 31) == 0) red[tid >> 5] = s;
    __syncthreads();
    if (tid == 0) {
        float t = 0.f;
#pragma unroll
        for (int w = 0; w < 8; w++) t += red[w];
        s_inv = rsqrtf(t * (1.0f / DMODEL) + 1e-5f);
    }
    __syncthreads();
    const float iv = s_inv;
    const float4 g4 = ((const float4*)gw)[tid];
    float a0 = v.x * iv * g4.x, a1 = v.y * iv * g4.y;
    float a2 = v.z * iv * g4.z, a3 = v.w * iv * g4.w;
    __half2* ph = (__half2*)(g_o16 + (size_t)row * DMODEL) + tid * 2;
    ph[0] = __halves2half2(__float2half_rn(a0), __float2half_rn(a1));
    ph[1] = __halves2half2(__float2half_rn(a2), __float2half_rn(a3));
}

// =====================================================================
extern "C" void kernel_launch(void* const* d_in, const int* in_sizes, int n_in,
                              void* d_out, int out_size)
{
    const float* x  = (const float*)d_in[0];
    const float* Wq = (const float*)d_in[1];
    const float* Wf = (const float*)d_in[2];
    const float* Wi = (const float*)d_in[3];
    const float* gw = (const float*)d_in[4];
    const float* Wo = (const float*)d_in[5];
    float* out = (float*)d_out;

    cudaFuncSetAttribute(gemm_mma<0>, cudaFuncAttributeMaxDynamicSharedMemorySize, SMEM_GEMM);
    cudaFuncSetAttribute(gemm_mma<1>, cudaFuncAttributeMaxDynamicSharedMemorySize, SMEM_GEMM);

    const int n4x = MROWS * DMODEL / 4;
    const int n4w = DMODEL * DMODEL / 4;
    round_kernel<<<n4x / 256, 256>>>(x,  0, 0, n4x);
    round_kernel<<<n4w / 256, 256>>>(Wq, 1, 0 * DMODEL * DMODEL, n4w);
    round_kernel<<<n4w / 256, 256>>>(Wf, 1, 1 * DMODEL * DMODEL, n4w);
    round_kernel<<<n4w / 256, 256>>>(Wi, 1, 2 * DMODEL * DMODEL, n4w);
    round_kernel<<<n4w / 256, 256>>>(Wo, 2, 0, n4w);

    gemm_mma<0><<<dim3(24, 64), 256, SMEM_GEMM>>>(nullptr);
    recur_kernel<<<dim3(8, 16), 128>>>();
    rms_round_kernel<<<MROWS, 256>>>(gw);
    gemm_mma<1><<<dim3(8, 64), 256, SMEM_GEMM>>>(out);
}

// round 9
// speedup vs baseline: 3.0966x; 1.0428x over previous
#include <cuda_runtime.h>
#include <cuda_bf16.h>
#include <cuda_fp16.h>
#include <cstdint>
#include <cstdio>

// Problem constants
#define T_LEN 4096
#define BATCH 2
#define DMODEL 1024
#define NH 8
#define DFH 128
#define DIH 128
#define BH (BATCH*NH)
#define MROWS (BATCH*T_LEN)

// ---------------- scratch (device globals; no runtime allocation) ----------------
__device__ float g_q[BH*T_LEN*DFH];   // silu(xWq^T) * DF^-0.5, layout [bh][t][f]
__device__ float g_e[BH*T_LEN*DFH];   // sigmoid(xWf^T)
__device__ float g_v[BH*T_LEN*DIH];   // xWi^T
__device__ float g_o[(size_t)MROWS*DMODEL];

// fp16 operands (single-term round-to-nearest)
__device__ __half g_x16[(size_t)MROWS*DMODEL];
__device__ __half g_w16[(size_t)3*DMODEL*DMODEL];   // Wq|Wf|Wi rows
__device__ __half g_o16[(size_t)MROWS*DMODEL];
__device__ __half g_wo16[(size_t)DMODEL*DMODEL];

// ---------------- helpers ----------------
__device__ __forceinline__ void cp16(void* s, const void* g) {
    uint32_t sa = (uint32_t)__cvta_generic_to_shared(s);
    asm volatile("cp.async.ca.shared.global [%0], [%1], 16;\n" :: "r"(sa), "l"(g));
}
__device__ __forceinline__ void cp16s(uint32_t sa, const void* g) {
    asm volatile("cp.async.ca.shared.global [%0], [%1], 16;\n" :: "r"(sa), "l"(g));
}
__device__ __forceinline__ uint32_t smem_u32(const void* p) {
    return (uint32_t)__cvta_generic_to_shared(p);
}

#define MMA_F16(accp, A, B)                                                  \
    asm("mma.sync.aligned.m16n8k16.row.col.f32.f16.f16.f32 "                 \
        "{%0,%1,%2,%3}, {%4,%5,%6,%7}, {%8,%9}, {%0,%1,%2,%3};"              \
        : "+f"((accp)[0]), "+f"((accp)[1]), "+f"((accp)[2]), "+f"((accp)[3]) \
        : "r"((A)[0]), "r"((A)[1]), "r"((A)[2]), "r"((A)[3]),                \
          "r"((B)[0]), "r"((B)[1]))

// =====================================================================
// rounding kernels: fp32 -> fp16
// =====================================================================
__global__ void round_x_kernel(const float* __restrict__ src, int n4)
{
    int i = blockIdx.x * blockDim.x + threadIdx.x;
    if (i >= n4) return;
    float4 v = ((const float4*)src)[i];
    __half2* p = (__half2*)(g_x16 + (size_t)4 * i);
    p[0] = __halves2half2(__float2half_rn(v.x), __float2half_rn(v.y));
    p[1] = __halves2half2(__float2half_rn(v.z), __float2half_rn(v.w));
}

// all 4 weight matrices in one launch; blockIdx.y selects
__global__ void round_w_kernel(const float* __restrict__ wq,
                               const float* __restrict__ wf,
                               const float* __restrict__ wi,
                               const float* __restrict__ wo)
{
    const int mat = blockIdx.y;
    const float* src = (mat == 0) ? wq : (mat == 1) ? wf : (mat == 2) ? wi : wo;
    __half* dst = (mat < 3) ? (g_w16 + (size_t)mat * DMODEL * DMODEL) : g_wo16;
    int i = blockIdx.x * blockDim.x + threadIdx.x;
    float4 v = ((const float4*)src)[i];
    __half2* p = (__half2*)(dst + (size_t)4 * i);
    p[0] = __halves2half2(__float2half_rn(v.x), __float2half_rn(v.y));
    p[1] = __halves2half2(__float2half_rn(v.z), __float2half_rn(v.w));
}

// =====================================================================
// fp16 HMMA GEMM: C = A16 @ B16^T, fp32 acc.
// CTA 128x128, BK=32 per stage (2 MMA K-steps per sync), 8 warps of 64x32,
// 3-stage cp.async.  Rows padded to 80B -> conflict-free ldmatrix.
// EPI=0: A=X, B=Wq|Wf|Wi, activation scatter.  EPI=1: A=o, B=Wo -> out.
// =====================================================================
#define NSTG      3
#define ROWB      80
#define OFF_B     10240            // 128 rows * 80
#define STG_BYTES 20480
#define SMEM_GEMM (NSTG * STG_BYTES)   // 61440

template<int EPI>
__global__ void __launch_bounds__(256, 2) gemm_mma(float* __restrict__ out)
{
    extern __shared__ char sm[];
    const uint32_t sb = smem_u32(sm);

    const __half* __restrict__ Ap = (EPI == 0) ? g_x16 : g_o16;
    const __half* __restrict__ Bp = (EPI == 0) ? g_w16 : g_wo16;

    const int tid  = threadIdx.x;
    const int wid  = tid >> 5, lane = tid & 31;
    const int wm   = wid >> 2, wn = wid & 3;
    const int m0   = blockIdx.y * 128;
    const int n0   = blockIdx.x * 128;

    const int srow = tid >> 1;          // 0..127
    const int sc2  = (tid & 1) * 32;    // byte offset of 2-chunk pair

    auto stage = [&](int stg, int kt) {
        const uint32_t dst = sb + stg * STG_BYTES + srow * ROWB + sc2;
        const size_t ao = (size_t)(m0 + srow) * 2048 + kt * 64 + sc2; // bytes
        const size_t bo = (size_t)(n0 + srow) * 2048 + kt * 64 + sc2;
        cp16s(dst,              (const char*)Ap + ao);
        cp16s(dst + 16,         (const char*)Ap + ao + 16);
        cp16s(dst + OFF_B,      (const char*)Bp + bo);
        cp16s(dst + OFF_B + 16, (const char*)Bp + bo + 16);
    };

    float acc[4][4][4];
#pragma unroll
    for (int i = 0; i < 4; i++)
#pragma unroll
        for (int j = 0; j < 4; j++)
#pragma unroll
            for (int r = 0; r < 4; r++) acc[i][j][r] = 0.f;

    // ldmatrix lane geometry
    const int aRowOff = wm * 64 + ((lane >> 3) & 1) * 8 + (lane & 7);   // + mf*16
    const int aColB   = (lane >> 4) * 16;                                // byte offset
    const int grp     = lane >> 3;
    const int bRowOff = wn * 32 + (grp >> 1) * 8 + (lane & 7);           // + nfp*16
    const int bColB   = (grp & 1) * 16;

    stage(0, 0);
    asm volatile("cp.async.commit_group;\n");
    stage(1, 1);
    asm volatile("cp.async.commit_group;\n");

    const int NKT = DMODEL / 32;  // 32 double-K iterations
    for (int kt = 0; kt < NKT; kt++) {
        if (kt < NKT - 1) asm volatile("cp.async.wait_group 1;\n");
        else              asm volatile("cp.async.wait_group 0;\n");
        __syncthreads();
        if (kt + 2 < NKT) {
            stage((kt + 2) % NSTG, kt + 2);
            asm volatile("cp.async.commit_group;\n");
        }

        const uint32_t tb = sb + (kt % NSTG) * STG_BYTES;

#pragma unroll
        for (int ks = 0; ks < 2; ks++) {
            const int colk = ks * 32;
            uint32_t bh[4][2];
#pragma unroll
            for (int nfp = 0; nfp < 2; nfp++) {
                uint32_t addr = tb + OFF_B + (bRowOff + nfp * 16) * ROWB + colk + bColB;
                asm volatile("ldmatrix.sync.aligned.m8n8.x4.shared.b16 {%0,%1,%2,%3}, [%4];"
                             : "=r"(bh[nfp*2][0]), "=r"(bh[nfp*2][1]),
                               "=r"(bh[nfp*2+1][0]), "=r"(bh[nfp*2+1][1]) : "r"(addr));
            }
#pragma unroll
            for (int mf = 0; mf < 4; mf++) {
                uint32_t a[4];
                uint32_t pa = tb + (aRowOff + mf * 16) * ROWB + colk + aColB;
                asm volatile("ldmatrix.sync.aligned.m8n8.x4.shared.b16 {%0,%1,%2,%3}, [%4];"
                             : "=r"(a[0]), "=r"(a[1]), "=r"(a[2]), "=r"(a[3]) : "r"(pa));
#pragma unroll
                for (int nf = 0; nf < 4; nf++) MMA_F16(acc[mf][nf], a, bh[nf]);
            }
        }
    }

    // epilogue
    const int g = lane >> 2, tg = lane & 3;
    if (EPI == 0) {
        const int mat = blockIdx.x >> 3;
        const int h   = blockIdx.x & 7;
        const float qscale = 0.08838834764831845f; // 128^-0.5
#pragma unroll
        for (int mf = 0; mf < 4; mf++)
#pragma unroll
        for (int nf = 0; nf < 4; nf++)
#pragma unroll
        for (int half = 0; half < 2; half++) {
            int m = m0 + wm * 64 + mf * 16 + g + half * 8;
            int f = wn * 32 + nf * 8 + tg * 2;
            int b = m >> 12, t = m & (T_LEN - 1);
            size_t base = (((size_t)(b * NH + h)) * T_LEN + t) * DFH + f;
            float y0 = acc[mf][nf][half * 2 + 0];
            float y1 = acc[mf][nf][half * 2 + 1];
            if (mat == 0) {
                float s0 = 1.f / (1.f + expf(-y0));
                float s1 = 1.f / (1.f + expf(-y1));
                *(float2*)(g_q + base) = make_float2(y0 * s0 * qscale, y1 * s1 * qscale);
            } else if (mat == 1) {
                float a0 = 1.f / (1.f + expf(-y0));
                float a1 = 1.f / (1.f + expf(-y1));
                *(float2*)(g_e + base) = make_float2(a0, a1);
            } else {
                *(float2*)(g_v + base) = make_float2(y0, y1);
            }
        }
    } else {
#pragma unroll
        for (int mf = 0; mf < 4; mf++)
#pragma unroll
        for (int nf = 0; nf < 4; nf++)
#pragma unroll
        for (int half = 0; half < 2; half++) {
            int m = m0 + wm * 64 + mf * 16 + g + half * 8;
            int n = n0 + wn * 32 + nf * 8 + tg * 2;
            *(float2*)(out + (size_t)m * DMODEL + n) =
                make_float2(acc[mf][nf][half * 2 + 0], acc[mf][nf][half * 2 + 1]);
        }
    }
}

// =====================================================================
// recurrence.  grid (8 dchunks, 16 bh), 128 threads.
// thread owns [8f x 2d] state.  S = fma(e, S - v, v)  [== e*S + (1-e)*v]
// =====================================================================
__global__ void __launch_bounds__(128) recur_kernel()
{
    __shared__ float sE[2][8][128];
    __shared__ float sQ[2][8][128];
    __shared__ float sV[2][8][16];
    __shared__ float sO[8 * 16 * 17];

    const int tid    = threadIdx.x;
    const int dchunk = blockIdx.x;   // 0..7
    const int bh     = blockIdx.y;   // 0..15
    const int d0 = dchunk * 16;
    const int fg = tid >> 3, dl = tid & 7, f0 = fg * 8;
    const int b = bh >> 3, h = bh & 7;
    const size_t bhbase = (size_t)bh * T_LEN * DFH;

    float S[16];
#pragma unroll
    for (int j = 0; j < 16; j++) S[j] = 0.f;

    auto stage = [&](int buf, int t0) {
#pragma unroll
        for (int p = 0; p < 2; p++) {
            int c = tid + p * 128;
            int s = c >> 5;
            int off = (c & 31) * 4;
            size_t gi = bhbase + (size_t)(t0 + s) * DFH + off;
            cp16(&sE[buf][s][off], g_e + gi);
            cp16(&sQ[buf][s][off], g_q + gi);
        }
        if (tid < 32) {
            int s = tid >> 2, off = (tid & 3) * 4;
            cp16(&sV[buf][s][off], g_v + bhbase + (size_t)(t0 + s) * DIH + d0 + off);
        }
    };

    stage(0, 0);
    asm volatile("cp.async.commit_group;\n");

    const int NBLK = T_LEN / 8;  // 512
    for (int blk = 0; blk < NBLK; blk++) {
        if (blk + 1 < NBLK) {
            stage((blk + 1) & 1, (blk + 1) * 8);
            asm volatile("cp.async.commit_group;\n");
            asm volatile("cp.async.wait_group 1;\n");
        } else {
            asm volatile("cp.async.wait_group 0;\n");
        }
        __syncthreads();

        const int cur = blk & 1;
#pragma unroll
        for (int s = 0; s < 8; s++) {
            float4 e0 = *(const float4*)&sE[cur][s][f0];
            float4 e1 = *(const float4*)&sE[cur][s][f0 + 4];
            float4 q0 = *(const float4*)&sQ[cur][s][f0];
            float4 q1 = *(const float4*)&sQ[cur][s][f0 + 4];
            float2 vv = *(const float2*)&sV[cur][s][dl * 2];
            float ev[8], qv[8];
            *(float4*)&ev[0] = e0; *(float4*)&ev[4] = e1;
            *(float4*)&qv[0] = q0; *(float4*)&qv[4] = q1;
            float o0 = 0.f, o1 = 0.f;
#pragma unroll
            for (int j = 0; j < 8; j++) {
                // e*S + (1-e)*v == fma(e, S-v, v)
                S[j * 2]     = fmaf(ev[j], S[j * 2]     - vv.x, vv.x);
                S[j * 2 + 1] = fmaf(ev[j], S[j * 2 + 1] - vv.y, vv.y);
                o0 = fmaf(qv[j], S[j * 2],     o0);
                o1 = fmaf(qv[j], S[j * 2 + 1], o1);
            }
            sO[(s * 16 + dl * 2 + 0) * 17 + fg] = o0;
            sO[(s * 16 + dl * 2 + 1) * 17 + fg] = o1;
        }
        __syncthreads();

        {
            const int tt = tid >> 4, dd = tid & 15;
            float acc = 0.f;
#pragma unroll
            for (int g2 = 0; g2 < 16; g2++) acc += sO[(tt * 16 + dd) * 17 + g2];
            const int trow = blk * 8 + tt;
            g_o[((size_t)(b * T_LEN + trow)) * DMODEL + h * DFH + d0 + dd] = acc;
        }
    }
}

// =====================================================================
// fused RMSNorm + gw scale + fp16 round of o
// =====================================================================
__global__ void rms_round_kernel(const float* __restrict__ gw)
{
    __shared__ float red[8];
    __shared__ float s_inv;
    const int row = blockIdx.x;
    const int tid = threadIdx.x;   // 256
    const float4 v = ((const float4*)(g_o + (size_t)row * DMODEL))[tid];
    float s = v.x * v.x + v.y * v.y + v.z * v.z + v.w * v.w;
#pragma unroll
    for (int o = 16; o > 0; o >>= 1) s += __shfl_xor_sync(0xffffffffu, s, o);
    if ((tid & 31) == 0) red[tid >> 5] = s;
    __syncthreads();
    if (tid == 0) {
        float t = 0.f;
#pragma unroll
        for (int w = 0; w < 8; w++) t += red[w];
        s_inv = rsqrtf(t * (1.0f / DMODEL) + 1e-5f);
    }
    __syncthreads();
    const float iv = s_inv;
    const float4 g4 = ((const float4*)gw)[tid];
    float a0 = v.x * iv * g4.x, a1 = v.y * iv * g4.y;
    float a2 = v.z * iv * g4.z, a3 = v.w * iv * g4.w;
    __half2* ph = (__half2*)(g_o16 + (size_t)row * DMODEL) + tid * 2;
    ph[0] = __halves2half2(__float2half_rn(a0), __float2half_rn(a1));
    ph[1] = __halves2half2(__float2half_rn(a2), __float2half_rn(a3));
}

// =====================================================================
extern "C" void kernel_launch(void* const* d_in, const int* in_sizes, int n_in,
                              void* d_out, int out_size)
{
    const float* x  = (const float*)d_in[0];
    const float* Wq = (const float*)d_in[1];
    const float* Wf = (const float*)d_in[2];
    const float* Wi = (const float*)d_in[3];
    const float* gw = (const float*)d_in[4];
    const float* Wo = (const float*)d_in[5];
    float* out = (float*)d_out;

    cudaFuncSetAttribute(gemm_mma<0>, cudaFuncAttributeMaxDynamicSharedMemorySize, SMEM_GEMM);
    cudaFuncSetAttribute(gemm_mma<1>, cudaFuncAttributeMaxDynamicSharedMemorySize, SMEM_GEMM);

    const int n4x = MROWS * DMODEL / 4;
    const int n4w = DMODEL * DMODEL / 4;
    round_x_kernel<<<n4x / 256, 256>>>(x, n4x);
    round_w_kernel<<<dim3(n4w / 256, 4), 256>>>(Wq, Wf, Wi, Wo);

    gemm_mma<0><<<dim3(24, 64), 256, SMEM_GEMM>>>(nullptr);
    recur_kernel<<<dim3(8, 16), 128>>>();
    rms_round_kernel<<<MROWS, 256>>>(gw);
    gemm_mma<1><<<dim3(8, 64), 256, SMEM_GEMM>>>(out);
}